// round 4
// baseline (speedup 1.0000x reference)
#include <cuda_runtime.h>
#include <math.h>
#include <stdint.h>

// ---------------- problem constants ----------------
#define BB 128
#define CC 3
#define IMG 224
#define PP 16
#define HP 14
#define NP 196
#define SS 197
#define DD 384
#define HEADS 6
#define HD 64
#define DEPTH 12
#define HID 1536
#define NCLS 100
#define PATCH_DIM 768
#define TOK (BB*SS)    // 25216 = 197*128
#define PTOK (BB*NP)   // 25088 = 196*128
#define BH (BB*HEADS)  // 768

// ---------------- scratch ----------------
__device__ float g_patches[PTOK * PATCH_DIM];
__device__ float g_tok[PTOK * DD];
__device__ float g_h[TOK * DD];
__device__ float g_xn[TOK * DD];
__device__ float g_qkv[TOK * 3 * DD];
__device__ float g_scores[(size_t)BH * SS * SS];
__device__ float g_ctx[TOK * DD];
__device__ float g_hid[TOK * HID];
__device__ float g_cls[BB * DD];
// tf32-rounded weights (offsets in floats)
#define W_PATCH 0
#define W_QKV   294912
#define W_OUT   5603328
#define W_FC1   7372800
#define W_FC2   14450688
#define W_TOTAL 21528576
__device__ float g_w[W_TOTAL];

// ---------------- helpers ----------------
__device__ __forceinline__ float tf32r(float x) {
    uint32_t u;
    asm("cvt.rna.tf32.f32 %0, %1;" : "=r"(u) : "f"(x));
    return __uint_as_float(u);
}
__device__ __forceinline__ uint32_t smem_u32(const void* p) {
    return (uint32_t)__cvta_generic_to_shared(p);
}
#define CPA(dst, src) asm volatile("cp.async.cg.shared.global [%0], [%1], 16;" :: "r"(dst), "l"(src))
#define CPC() asm volatile("cp.async.commit_group;")
#define CPW0() asm volatile("cp.async.wait_group 0;")
#define CPW1() asm volatile("cp.async.wait_group 1;")
#define MMA_TF32(d, a, b) asm volatile( \
    "mma.sync.aligned.m16n8k8.row.col.f32.tf32.tf32.f32 " \
    "{%0,%1,%2,%3},{%4,%5,%6,%7},{%8,%9},{%0,%1,%2,%3};" \
    : "+f"(d[0]), "+f"(d[1]), "+f"(d[2]), "+f"(d[3]) \
    : "r"(a[0]), "r"(a[1]), "r"(a[2]), "r"(a[3]), "r"(b[0]), "r"(b[1]))

// ---------------- merged weight rounding (one launch) ----------------
__global__ void round_all_kernel(const float* __restrict__ pw, const float* __restrict__ qw,
                                 const float* __restrict__ ow, const float* __restrict__ f1,
                                 const float* __restrict__ f2, float* __restrict__ w) {
    int i = blockIdx.x * blockDim.x + threadIdx.x;
    if (i >= W_TOTAL / 4) return;
    int f = i * 4;
    const float* src; int off;
    if (f < W_QKV)      { src = pw; off = f - W_PATCH; }
    else if (f < W_OUT) { src = qw; off = f - W_QKV; }
    else if (f < W_FC1) { src = ow; off = f - W_OUT; }
    else if (f < W_FC2) { src = f1; off = f - W_FC1; }
    else                { src = f2; off = f - W_FC2; }
    float4 v = *(const float4*)(src + off);
    v.x = tf32r(v.x); v.y = tf32r(v.y); v.z = tf32r(v.z); v.w = tf32r(v.w);
    ((float4*)w)[i] = v;
}

// ---------------- patchify (+tf32 round) ----------------
__global__ void patchify_kernel(const float* __restrict__ x, float* __restrict__ patches) {
    int idx = blockIdx.x * blockDim.x + threadIdx.x;
    if (idx >= PTOK * PATCH_DIM) return;
    int t = idx / PATCH_DIM;
    int k = idx - t * PATCH_DIM;
    int b = t / NP;
    int n = t - b * NP;
    int ph = n / HP, pw = n - ph * HP;
    int c = k >> 8;
    int py = (k >> 4) & 15;
    int px = k & 15;
    patches[idx] = tf32r(x[(((size_t)b * CC + c) * IMG + (ph * PP + py)) * IMG + (pw * PP + px)]);
}

// ---------------- assemble h = [cls; tok] + pos ----------------
__global__ void assemble_kernel(const float* __restrict__ tok, const float* __restrict__ cls_token,
                                const float* __restrict__ pos, float* __restrict__ h) {
    int idx = blockIdx.x * blockDim.x + threadIdx.x;
    if (idx >= TOK * DD) return;
    int row = idx / DD;
    int d = idx - row * DD;
    int b = row / SS;
    int s = row - b * SS;
    float v = (s == 0) ? cls_token[d] : tok[((size_t)b * NP + (s - 1)) * DD + d];
    h[idx] = v + pos[s * DD + d];
}

// ---------------- tf32 tensor-core NT GEMM ----------------
#define BMT 128
#define BNT 128
#define BKT 16
#define SST 20

template <int OP>
__global__ void __launch_bounds__(256) gemm_tf32(
    const float* __restrict__ A, const float* __restrict__ Bw,
    const float* __restrict__ bias, const float* __restrict__ res,
    float* __restrict__ C, int M, int N, int K)
{
    __shared__ __align__(16) float As[2][BMT][SST];
    __shared__ __align__(16) float Bs[2][BMT][SST];

    const int tid = threadIdx.x;
    const int lane = tid & 31, warp = tid >> 5;
    const int wm = (warp >> 1) * 32;
    const int wn = (warp & 1) * 64;
    const int r = lane >> 2, cq = lane & 3;
    const int m0 = blockIdx.y * BMT, n0 = blockIdx.x * BNT;

    const int lrow = tid >> 2;
    const int lcol = (tid & 3) * 4;
    const float* Ag0 = A + (size_t)(m0 + lrow) * K + lcol;
    const float* Ag1 = A + (size_t)(m0 + lrow + 64) * K + lcol;
    const float* Bg0 = Bw + (size_t)(n0 + lrow) * K + lcol;
    const float* Bg1 = Bw + (size_t)(n0 + lrow + 64) * K + lcol;
    uint32_t dA0[2], dA1[2], dB0[2], dB1[2];
#pragma unroll
    for (int s = 0; s < 2; s++) {
        dA0[s] = smem_u32(&As[s][lrow][lcol]);
        dA1[s] = smem_u32(&As[s][lrow + 64][lcol]);
        dB0[s] = smem_u32(&Bs[s][lrow][lcol]);
        dB1[s] = smem_u32(&Bs[s][lrow + 64][lcol]);
    }

    float acc[2][8][4];
#pragma unroll
    for (int mt = 0; mt < 2; mt++)
#pragma unroll
        for (int nt = 0; nt < 8; nt++)
#pragma unroll
            for (int i = 0; i < 4; i++) acc[mt][nt][i] = 0.f;

    const int KT = K / BKT;
    CPA(dA0[0], Ag0); CPA(dA1[0], Ag1); CPA(dB0[0], Bg0); CPA(dB1[0], Bg1);
    CPC();

    for (int kt = 0; kt < KT; kt++) {
        const int buf = kt & 1;
        if (kt + 1 < KT) {
            const int nb = buf ^ 1;
            const int ko = (kt + 1) * BKT;
            CPA(dA0[nb], Ag0 + ko); CPA(dA1[nb], Ag1 + ko);
            CPA(dB0[nb], Bg0 + ko); CPA(dB1[nb], Bg1 + ko);
            CPC();
            CPW1();
        } else {
            CPW0();
        }
        __syncthreads();

#pragma unroll
        for (int ks = 0; ks < 2; ks++) {
            const int k0 = ks * 8;
            uint32_t a[2][4], b[8][2];
#pragma unroll
            for (int mt = 0; mt < 2; mt++) {
                const float* ap = &As[buf][wm + mt * 16 + r][k0 + cq];
                a[mt][0] = __float_as_uint(ap[0]);
                a[mt][1] = __float_as_uint(ap[8 * SST]);
                a[mt][2] = __float_as_uint(ap[4]);
                a[mt][3] = __float_as_uint(ap[8 * SST + 4]);
            }
#pragma unroll
            for (int nt = 0; nt < 8; nt++) {
                const float* bp = &Bs[buf][wn + nt * 8 + r][k0 + cq];
                b[nt][0] = __float_as_uint(bp[0]);
                b[nt][1] = __float_as_uint(bp[4]);
            }
#pragma unroll
            for (int mt = 0; mt < 2; mt++)
#pragma unroll
                for (int nt = 0; nt < 8; nt++)
                    MMA_TF32(acc[mt][nt], a[mt], b[nt]);
        }
        __syncthreads();
    }

#pragma unroll
    for (int mt = 0; mt < 2; mt++) {
        const int row = m0 + wm + mt * 16 + r;
#pragma unroll
        for (int nt = 0; nt < 8; nt++) {
            const int col = n0 + wn + nt * 8 + cq * 2;
            const float2 bv = *(const float2*)(bias + col);
            float o0 = acc[mt][nt][0] + bv.x;
            float o1 = acc[mt][nt][1] + bv.y;
            float o2 = acc[mt][nt][2] + bv.x;
            float o3 = acc[mt][nt][3] + bv.y;
            if (OP == 1) {
                o0 = tf32r(0.5f * o0 * (1.0f + erff(o0 * 0.7071067811865475f)));
                o1 = tf32r(0.5f * o1 * (1.0f + erff(o1 * 0.7071067811865475f)));
                o2 = tf32r(0.5f * o2 * (1.0f + erff(o2 * 0.7071067811865475f)));
                o3 = tf32r(0.5f * o3 * (1.0f + erff(o3 * 0.7071067811865475f)));
            }
            if (OP == 2) {
                const float2 r0 = *(const float2*)(res + (size_t)row * N + col);
                const float2 r1 = *(const float2*)(res + (size_t)(row + 8) * N + col);
                o0 += r0.x; o1 += r0.y; o2 += r1.x; o3 += r1.y;
            }
            *(float2*)(C + (size_t)row * N + col) = make_float2(o0, o1);
            *(float2*)(C + (size_t)(row + 8) * N + col) = make_float2(o2, o3);
        }
    }
}

// ---------------- LayerNorm (tf32-rounded output) ----------------
__global__ void ln_kernel(const float* __restrict__ x, const float* __restrict__ g,
                          const float* __restrict__ bt, float* __restrict__ y,
                          long in_row_stride)
{
    const int row = blockIdx.x;
    const int tid = threadIdx.x;
    const float* xr = x + (size_t)row * in_row_stride;
    float v = xr[tid];
    float s = v, q = v * v;
#pragma unroll
    for (int o = 16; o; o >>= 1) {
        s += __shfl_down_sync(0xffffffffu, s, o);
        q += __shfl_down_sync(0xffffffffu, q, o);
    }
    __shared__ float sh[12], sh2[12];
    int w = tid >> 5, lane = tid & 31;
    if (lane == 0) { sh[w] = s; sh2[w] = q; }
    __syncthreads();
    if (tid < 32) {
        float ss = (tid < 12) ? sh[tid] : 0.f;
        float qq = (tid < 12) ? sh2[tid] : 0.f;
#pragma unroll
        for (int o = 16; o; o >>= 1) {
            ss += __shfl_down_sync(0xffffffffu, ss, o);
            qq += __shfl_down_sync(0xffffffffu, qq, o);
        }
        if (tid == 0) {
            float mean = ss * (1.0f / DD);
            float var = qq * (1.0f / DD) - mean * mean;
            sh[0] = mean;
            sh2[0] = rsqrtf(var + 1e-5f);
        }
    }
    __syncthreads();
    float mean = sh[0], rstd = sh2[0];
    y[(size_t)row * DD + tid] = tf32r((v - mean) * rstd * g[tid] + bt[tid]);
}

// ---------------- attention scores, 3xTF32 tensor cores ----------------
__global__ void __launch_bounds__(256) attn_scores_tc(const float* __restrict__ qkv,
                                                      float* __restrict__ scores)
{
    extern __shared__ float sm[];
    float (*Qhi)[68] = (float(*)[68])sm;
    float (*Qlo)[68] = Qhi + 64;
    float (*Khi)[68] = Qlo + 64;
    float (*Klo)[68] = Khi + 64;

    const int bh = blockIdx.z;
    const int b = bh / HEADS, h = bh - b * HEADS;
    const int i0 = blockIdx.y * 64, j0 = blockIdx.x * 64;
    const float* base = qkv + (size_t)b * SS * (3 * DD) + h * HD;

    for (int idx = threadIdx.x; idx < 4096; idx += 256) {
        int ii = idx >> 6, d = idx & 63;
        int i = i0 + ii;
        float q = (i < SS) ? base[(size_t)i * (3 * DD) + d] * 0.125f : 0.f;
        float qh = tf32r(q);
        Qhi[ii][d] = qh; Qlo[ii][d] = tf32r(q - qh);
        int j = j0 + ii;
        float k = (j < SS) ? base[(size_t)j * (3 * DD) + DD + d] : 0.f;
        float kh = tf32r(k);
        Khi[ii][d] = kh; Klo[ii][d] = tf32r(k - kh);
    }
    __syncthreads();

    const int lane = threadIdx.x & 31, warp = threadIdx.x >> 5;
    const int wm = (warp >> 1) * 16;
    const int wn = (warp & 1) * 32;
    const int r = lane >> 2, cq = lane & 3;

    float acc[4][4];
#pragma unroll
    for (int nt = 0; nt < 4; nt++)
#pragma unroll
        for (int i = 0; i < 4; i++) acc[nt][i] = 0.f;

#pragma unroll
    for (int k0 = 0; k0 < 64; k0 += 8) {
        uint32_t ahi[4], alo[4];
        const float* aph = &Qhi[wm + r][k0 + cq];
        const float* apl = &Qlo[wm + r][k0 + cq];
        ahi[0] = __float_as_uint(aph[0]);      alo[0] = __float_as_uint(apl[0]);
        ahi[1] = __float_as_uint(aph[8 * 68]); alo[1] = __float_as_uint(apl[8 * 68]);
        ahi[2] = __float_as_uint(aph[4]);      alo[2] = __float_as_uint(apl[4]);
        ahi[3] = __float_as_uint(aph[8 * 68 + 4]); alo[3] = __float_as_uint(apl[8 * 68 + 4]);
#pragma unroll
        for (int nt = 0; nt < 4; nt++) {
            const float* bph = &Khi[wn + nt * 8 + r][k0 + cq];
            const float* bpl = &Klo[wn + nt * 8 + r][k0 + cq];
            uint32_t bhi[2] = {__float_as_uint(bph[0]), __float_as_uint(bph[4])};
            uint32_t blo[2] = {__float_as_uint(bpl[0]), __float_as_uint(bpl[4])};
            MMA_TF32(acc[nt], ahi, bhi);
            MMA_TF32(acc[nt], ahi, blo);
            MMA_TF32(acc[nt], alo, bhi);
        }
    }

    // scalar stores: scores row stride (197 floats) is not 8B-aligned
#pragma unroll
    for (int nt = 0; nt < 4; nt++) {
        int col = j0 + wn + nt * 8 + cq * 2;
        int row0 = i0 + wm + r, row1 = row0 + 8;
        if (row0 < SS) {
            float* p = &scores[((size_t)bh * SS + row0) * SS + col];
            if (col < SS)     p[0] = acc[nt][0];
            if (col + 1 < SS) p[1] = acc[nt][1];
        }
        if (row1 < SS) {
            float* p = &scores[((size_t)bh * SS + row1) * SS + col];
            if (col < SS)     p[0] = acc[nt][2];
            if (col + 1 < SS) p[1] = acc[nt][3];
        }
    }
}

// ---------------- softmax ----------------
__global__ void softmax_kernel(float* __restrict__ scores, int nrows) {
    int row = blockIdx.x * 8 + (threadIdx.x >> 5);
    if (row >= nrows) return;
    int lane = threadIdx.x & 31;
    float* p = scores + (size_t)row * SS;
    float vals[7];
    float m = -1e30f;
#pragma unroll
    for (int t = 0; t < 7; t++) {
        int j = lane + 32 * t;
        vals[t] = (j < SS) ? p[j] : -1e30f;
        m = fmaxf(m, vals[t]);
    }
#pragma unroll
    for (int o = 16; o; o >>= 1) m = fmaxf(m, __shfl_xor_sync(0xffffffffu, m, o));
    float s = 0.f;
#pragma unroll
    for (int t = 0; t < 7; t++) {
        int j = lane + 32 * t;
        float e = (j < SS) ? expf(vals[t] - m) : 0.f;
        vals[t] = e;
        s += e;
    }
#pragma unroll
    for (int o = 16; o; o >>= 1) s += __shfl_xor_sync(0xffffffffu, s, o);
    float inv = 1.0f / s;
#pragma unroll
    for (int t = 0; t < 7; t++) {
        int j = lane + 32 * t;
        if (j < SS) p[j] = vals[t] * inv;
    }
}

// ---------------- ctx = attn @ v, 3xTF32 tensor cores ----------------
__global__ void __launch_bounds__(256) attn_ctx_tc(const float* __restrict__ scores,
                                                   const float* __restrict__ qkv,
                                                   float* __restrict__ ctx)
{
    extern __shared__ float sm[];
    float (*Phi)[68]  = (float(*)[68])sm;
    float (*Plo)[68]  = Phi + 64;
    float (*Vthi)[68] = Plo + 64;
    float (*Vtlo)[68] = Vthi + 64;

    const int bh = blockIdx.y;
    const int b = bh / HEADS, h = bh - b * HEADS;
    const int i0 = blockIdx.x * 64;
    const float* vbase = qkv + (size_t)b * SS * (3 * DD) + 2 * DD + h * HD;

    const int lane = threadIdx.x & 31, warp = threadIdx.x >> 5;
    const int wm = (warp >> 1) * 16;
    const int wn = (warp & 1) * 32;
    const int r = lane >> 2, cq = lane & 3;

    float acc[4][4];
#pragma unroll
    for (int nt = 0; nt < 4; nt++)
#pragma unroll
        for (int i = 0; i < 4; i++) acc[nt][i] = 0.f;

    for (int jc = 0; jc < 4; jc++) {
        const int jb = jc * 64;
        for (int idx = threadIdx.x; idx < 4096; idx += 256) {
            int ii = idx >> 6, jj = idx & 63;
            int i = i0 + ii, j = jb + jj;
            float p = (i < SS && j < SS) ? scores[((size_t)bh * SS + i) * SS + j] : 0.f;
            float ph = tf32r(p);
            Phi[ii][jj] = ph; Plo[ii][jj] = tf32r(p - ph);
        }
        for (int idx = threadIdx.x; idx < 4096; idx += 256) {
            int jj = idx >> 6, d = idx & 63;
            int j = jb + jj;
            float v = (j < SS) ? vbase[(size_t)j * (3 * DD) + d] : 0.f;
            float vh = tf32r(v);
            Vthi[d][jj] = vh; Vtlo[d][jj] = tf32r(v - vh);
        }
        __syncthreads();

#pragma unroll
        for (int k0 = 0; k0 < 64; k0 += 8) {
            uint32_t ahi[4], alo[4];
            const float* aph = &Phi[wm + r][k0 + cq];
            const float* apl = &Plo[wm + r][k0 + cq];
            ahi[0] = __float_as_uint(aph[0]);      alo[0] = __float_as_uint(apl[0]);
            ahi[1] = __float_as_uint(aph[8 * 68]); alo[1] = __float_as_uint(apl[8 * 68]);
            ahi[2] = __float_as_uint(aph[4]);      alo[2] = __float_as_uint(apl[4]);
            ahi[3] = __float_as_uint(aph[8 * 68 + 4]); alo[3] = __float_as_uint(apl[8 * 68 + 4]);
#pragma unroll
            for (int nt = 0; nt < 4; nt++) {
                const float* bph = &Vthi[wn + nt * 8 + r][k0 + cq];
                const float* bpl = &Vtlo[wn + nt * 8 + r][k0 + cq];
                uint32_t bhi[2] = {__float_as_uint(bph[0]), __float_as_uint(bph[4])};
                uint32_t blo[2] = {__float_as_uint(bpl[0]), __float_as_uint(bpl[4])};
                MMA_TF32(acc[nt], ahi, bhi);
                MMA_TF32(acc[nt], ahi, blo);
                MMA_TF32(acc[nt], alo, bhi);
            }
        }
        __syncthreads();
    }

#pragma unroll
    for (int nt = 0; nt < 4; nt++) {
        int col = h * HD + wn + nt * 8 + cq * 2;
        int row0 = i0 + wm + r, row1 = row0 + 8;
        if (row0 < SS) {
            float* cp = &ctx[((size_t)b * SS + row0) * DD + col];
            cp[0] = tf32r(acc[nt][0]); cp[1] = tf32r(acc[nt][1]);
        }
        if (row1 < SS) {
            float* cp = &ctx[((size_t)b * SS + row1) * DD + col];
            cp[0] = tf32r(acc[nt][2]); cp[1] = tf32r(acc[nt][3]);
        }
    }
}

// ---------------- classifier head ----------------
__global__ void head_kernel(const float* __restrict__ cls, const float* __restrict__ hw,
                            float* __restrict__ out)
{
    __shared__ float s[DD];
    int b = blockIdx.x;
    for (int k = threadIdx.x; k < DD; k += blockDim.x) s[k] = cls[(size_t)b * DD + k];
    __syncthreads();
    int c = threadIdx.x;
    if (c < NCLS) {
        const float* w = hw + (size_t)c * DD;
        float acc = 0.f;
#pragma unroll 8
        for (int k = 0; k < DD; k++) acc += s[k] * w[k];
        out[(size_t)b * NCLS + c] = acc;
    }
}

// ---------------- launch ----------------
extern "C" void kernel_launch(void* const* d_in, const int* in_sizes, int n_in,
                              void* d_out, int out_size) {
    const float* x         = (const float*)d_in[0];
    const float* patch_w   = (const float*)d_in[1];
    const float* patch_b   = (const float*)d_in[2];
    const float* cls_token = (const float*)d_in[3];
    const float* pos_embed = (const float*)d_in[4];
    const float* ln1_g     = (const float*)d_in[5];
    const float* ln1_b     = (const float*)d_in[6];
    const float* qkv_w     = (const float*)d_in[7];
    const float* qkv_b     = (const float*)d_in[8];
    const float* out_w     = (const float*)d_in[9];
    const float* out_b     = (const float*)d_in[10];
    const float* ln2_g     = (const float*)d_in[11];
    const float* ln2_b     = (const float*)d_in[12];
    const float* fc1_w     = (const float*)d_in[13];
    const float* fc1_b     = (const float*)d_in[14];
    const float* fc2_w     = (const float*)d_in[15];
    const float* fc2_b     = (const float*)d_in[16];
    const float* lnf_g     = (const float*)d_in[17];
    const float* lnf_b     = (const float*)d_in[18];
    const float* head_w    = (const float*)d_in[19];
    float* out = (float*)d_out;

    float *patches, *tok, *h, *xn, *qkv, *scores, *ctx, *hid, *cls, *w;
    cudaGetSymbolAddress((void**)&patches, g_patches);
    cudaGetSymbolAddress((void**)&tok, g_tok);
    cudaGetSymbolAddress((void**)&h, g_h);
    cudaGetSymbolAddress((void**)&xn, g_xn);
    cudaGetSymbolAddress((void**)&qkv, g_qkv);
    cudaGetSymbolAddress((void**)&scores, g_scores);
    cudaGetSymbolAddress((void**)&ctx, g_ctx);
    cudaGetSymbolAddress((void**)&hid, g_hid);
    cudaGetSymbolAddress((void**)&cls, g_cls);
    cudaGetSymbolAddress((void**)&w, g_w);

    const int ATT_SMEM = 4 * 64 * 68 * (int)sizeof(float);  // 69632
    cudaFuncSetAttribute(attn_scores_tc, cudaFuncAttributeMaxDynamicSharedMemorySize, ATT_SMEM);
    cudaFuncSetAttribute(attn_ctx_tc, cudaFuncAttributeMaxDynamicSharedMemorySize, ATT_SMEM);

    round_all_kernel<<<(W_TOTAL / 4 + 255) / 256, 256>>>(patch_w, qkv_w, out_w, fc1_w, fc2_w, w);
    patchify_kernel<<<(PTOK * PATCH_DIM + 255) / 256, 256>>>(x, patches);
    gemm_tf32<0><<<dim3(DD / 128, PTOK / 128), 256>>>(
        patches, w + W_PATCH, patch_b, nullptr, tok, PTOK, DD, PATCH_DIM);
    assemble_kernel<<<(TOK * DD + 255) / 256, 256>>>(tok, cls_token, pos_embed, h);

    for (int i = 0; i < DEPTH; i++) {
        ln_kernel<<<TOK, DD>>>(h, ln1_g + i * DD, ln1_b + i * DD, xn, DD);
        gemm_tf32<0><<<dim3(3 * DD / 128, TOK / 128), 256>>>(
            xn, w + W_QKV + (size_t)i * 3 * DD * DD, qkv_b + (size_t)i * 3 * DD,
            nullptr, qkv, TOK, 3 * DD, DD);
        attn_scores_tc<<<dim3(4, 4, BH), 256, ATT_SMEM>>>(qkv, scores);
        softmax_kernel<<<(BH * SS + 7) / 8, 256>>>(scores, BH * SS);
        attn_ctx_tc<<<dim3(4, BH), 256, ATT_SMEM>>>(scores, qkv, ctx);
        gemm_tf32<2><<<dim3(DD / 128, TOK / 128), 256>>>(
            ctx, w + W_OUT + (size_t)i * DD * DD, out_b + (size_t)i * DD, h, h, TOK, DD, DD);
        ln_kernel<<<TOK, DD>>>(h, ln2_g + i * DD, ln2_b + i * DD, xn, DD);
        gemm_tf32<1><<<dim3(HID / 128, TOK / 128), 256>>>(
            xn, w + W_FC1 + (size_t)i * HID * DD, fc1_b + (size_t)i * HID,
            nullptr, hid, TOK, HID, DD);
        gemm_tf32<2><<<dim3(DD / 128, TOK / 128), 256>>>(
            hid, w + W_FC2 + (size_t)i * DD * HID, fc2_b + (size_t)i * DD, h, h, TOK, DD, HID);
    }

    ln_kernel<<<BB, DD>>>(h, lnf_g, lnf_b, cls, (long)SS * DD);
    head_kernel<<<BB, 128>>>(cls, head_w, out);
}

// round 5
// speedup vs baseline: 1.1694x; 1.1694x over previous
#include <cuda_runtime.h>
#include <math.h>
#include <stdint.h>

// ---------------- problem constants ----------------
#define BB 128
#define CC 3
#define IMG 224
#define PP 16
#define HP 14
#define NP 196
#define SS 197
#define DD 384
#define HEADS 6
#define HD 64
#define DEPTH 12
#define HID 1536
#define NCLS 100
#define PATCH_DIM 768
#define TOK (BB*SS)    // 25216
#define PTOK (BB*NP)   // 25088
#define BH (BB*HEADS)  // 768

// ---------------- scratch ----------------
__device__ float g_patches[PTOK * PATCH_DIM];
__device__ float g_tok[PTOK * DD];
__device__ float g_h[TOK * DD];
__device__ float g_xn[TOK * DD];
__device__ float g_qkv[TOK * 3 * DD];
__device__ float g_ctx[TOK * DD];
__device__ float g_hid[TOK * HID];
__device__ float g_cls[BB * DD];
// tf32-rounded weights (offsets in floats)
#define W_PATCH 0
#define W_QKV   294912
#define W_OUT   5603328
#define W_FC1   7372800
#define W_FC2   14450688
#define W_TOTAL 21528576
__device__ float g_w[W_TOTAL];

// ---------------- helpers ----------------
__device__ __forceinline__ float tf32r(float x) {
    uint32_t u;
    asm("cvt.rna.tf32.f32 %0, %1;" : "=r"(u) : "f"(x));
    return __uint_as_float(u);
}
__device__ __forceinline__ void split32(float x, float& hi, float& lo) {
    hi = tf32r(x);
    lo = tf32r(x - hi);
}
__device__ __forceinline__ uint32_t smem_u32(const void* p) {
    return (uint32_t)__cvta_generic_to_shared(p);
}
#define CPA(dst, src) asm volatile("cp.async.cg.shared.global [%0], [%1], 16;" :: "r"(dst), "l"(src))
#define CPC() asm volatile("cp.async.commit_group;")
#define CPW0() asm volatile("cp.async.wait_group 0;")
#define CPW1() asm volatile("cp.async.wait_group 1;")
#define MMA_TF32(d, a, b) asm volatile( \
    "mma.sync.aligned.m16n8k8.row.col.f32.tf32.tf32.f32 " \
    "{%0,%1,%2,%3},{%4,%5,%6,%7},{%8,%9},{%0,%1,%2,%3};" \
    : "+f"(d[0]), "+f"(d[1]), "+f"(d[2]), "+f"(d[3]) \
    : "r"(a[0]), "r"(a[1]), "r"(a[2]), "r"(a[3]), "r"(b[0]), "r"(b[1]))

// ---------------- merged weight rounding ----------------
__global__ void round_all_kernel(const float* __restrict__ pw, const float* __restrict__ qw,
                                 const float* __restrict__ ow, const float* __restrict__ f1,
                                 const float* __restrict__ f2, float* __restrict__ w) {
    int i = blockIdx.x * blockDim.x + threadIdx.x;
    if (i >= W_TOTAL / 4) return;
    int f = i * 4;
    const float* src; int off;
    if (f < W_QKV)      { src = pw; off = f - W_PATCH; }
    else if (f < W_OUT) { src = qw; off = f - W_QKV; }
    else if (f < W_FC1) { src = ow; off = f - W_OUT; }
    else if (f < W_FC2) { src = f1; off = f - W_FC1; }
    else                { src = f2; off = f - W_FC2; }
    float4 v = *(const float4*)(src + off);
    v.x = tf32r(v.x); v.y = tf32r(v.y); v.z = tf32r(v.z); v.w = tf32r(v.w);
    ((float4*)w)[i] = v;
}

// ---------------- patchify (+tf32 round) ----------------
__global__ void patchify_kernel(const float* __restrict__ x, float* __restrict__ patches) {
    int idx = blockIdx.x * blockDim.x + threadIdx.x;
    if (idx >= PTOK * PATCH_DIM) return;
    int t = idx / PATCH_DIM;
    int k = idx - t * PATCH_DIM;
    int b = t / NP;
    int n = t - b * NP;
    int ph = n / HP, pw = n - ph * HP;
    int c = k >> 8;
    int py = (k >> 4) & 15;
    int px = k & 15;
    patches[idx] = tf32r(x[(((size_t)b * CC + c) * IMG + (ph * PP + py)) * IMG + (pw * PP + px)]);
}

// ---------------- assemble h = [cls; tok] + pos ----------------
__global__ void assemble_kernel(const float* __restrict__ tok, const float* __restrict__ cls_token,
                                const float* __restrict__ pos, float* __restrict__ h) {
    int idx = blockIdx.x * blockDim.x + threadIdx.x;
    if (idx >= TOK * DD) return;
    int row = idx / DD;
    int d = idx - row * DD;
    int b = row / SS;
    int s = row - b * SS;
    float v = (s == 0) ? cls_token[d] : tok[((size_t)b * NP + (s - 1)) * DD + d];
    h[idx] = v + pos[s * DD + d];
}

// ---------------- tf32 tensor-core NT GEMM, BK=32, 2-stage cp.async ----------------
#define GBK 32
#define GST 36
#define GEMM_SMEM (2 * 2 * 128 * GST * 4)   // 73728 B

template <int OP>
__global__ void __launch_bounds__(256, 2) gemm_tf32(
    const float* __restrict__ A, const float* __restrict__ Bw,
    const float* __restrict__ bias, const float* __restrict__ res,
    float* __restrict__ C, int M, int N, int K)
{
    extern __shared__ float gsm[];
    float* As = gsm;                   // [2][128][GST]
    float* Bs = gsm + 2 * 128 * GST;

    const int tid = threadIdx.x;
    const int lane = tid & 31, warp = tid >> 5;
    const int wm = (warp >> 1) * 32;
    const int wn = (warp & 1) * 64;
    const int r = lane >> 2, cq = lane & 3;
    const int m0 = blockIdx.y * 128, n0 = blockIdx.x * 128;

    const int lr = tid >> 3;           // 0..31
    const int lc = (tid & 7) * 4;      // 0..28
    const float* Ag = A + (size_t)(m0 + lr) * K + lc;
    const float* Bg = Bw + (size_t)(n0 + lr) * K + lc;
    uint32_t sA[2][4], sB[2][4];
#pragma unroll
    for (int s = 0; s < 2; s++)
#pragma unroll
        for (int c = 0; c < 4; c++) {
            sA[s][c] = smem_u32(As + (size_t)(s * 128 + lr + c * 32) * GST + lc);
            sB[s][c] = smem_u32(Bs + (size_t)(s * 128 + lr + c * 32) * GST + lc);
        }

    float acc[2][8][4];
#pragma unroll
    for (int mt = 0; mt < 2; mt++)
#pragma unroll
        for (int nt = 0; nt < 8; nt++)
#pragma unroll
            for (int i = 0; i < 4; i++) acc[mt][nt][i] = 0.f;

    const int KT = K / GBK;
#pragma unroll
    for (int c = 0; c < 4; c++) {
        CPA(sA[0][c], Ag + (size_t)c * 32 * K);
        CPA(sB[0][c], Bg + (size_t)c * 32 * K);
    }
    CPC();

    for (int kt = 0; kt < KT; kt++) {
        const int buf = kt & 1;
        if (kt + 1 < KT) {
            const int nb = buf ^ 1;
            const int ko = (kt + 1) * GBK;
#pragma unroll
            for (int c = 0; c < 4; c++) {
                CPA(sA[nb][c], Ag + (size_t)c * 32 * K + ko);
                CPA(sB[nb][c], Bg + (size_t)c * 32 * K + ko);
            }
            CPC();
            CPW1();
        } else {
            CPW0();
        }
        __syncthreads();

#pragma unroll
        for (int ks = 0; ks < 4; ks++) {
            const int k0 = ks * 8;
            uint32_t a[2][4], b[8][2];
#pragma unroll
            for (int mt = 0; mt < 2; mt++) {
                const float* ap = As + (size_t)(buf * 128 + wm + mt * 16 + r) * GST + k0 + cq;
                a[mt][0] = __float_as_uint(ap[0]);
                a[mt][1] = __float_as_uint(ap[8 * GST]);
                a[mt][2] = __float_as_uint(ap[4]);
                a[mt][3] = __float_as_uint(ap[8 * GST + 4]);
            }
#pragma unroll
            for (int nt = 0; nt < 8; nt++) {
                const float* bp = Bs + (size_t)(buf * 128 + wn + nt * 8 + r) * GST + k0 + cq;
                b[nt][0] = __float_as_uint(bp[0]);
                b[nt][1] = __float_as_uint(bp[4]);
            }
#pragma unroll
            for (int mt = 0; mt < 2; mt++)
#pragma unroll
                for (int nt = 0; nt < 8; nt++)
                    MMA_TF32(acc[mt][nt], a[mt], b[nt]);
        }
        __syncthreads();
    }

#pragma unroll
    for (int mt = 0; mt < 2; mt++) {
        const int row = m0 + wm + mt * 16 + r;
#pragma unroll
        for (int nt = 0; nt < 8; nt++) {
            const int col = n0 + wn + nt * 8 + cq * 2;
            const float2 bv = *(const float2*)(bias + col);
            float o0 = acc[mt][nt][0] + bv.x;
            float o1 = acc[mt][nt][1] + bv.y;
            float o2 = acc[mt][nt][2] + bv.x;
            float o3 = acc[mt][nt][3] + bv.y;
            if (OP == 1) {
                o0 = tf32r(0.5f * o0 * (1.0f + erff(o0 * 0.7071067811865475f)));
                o1 = tf32r(0.5f * o1 * (1.0f + erff(o1 * 0.7071067811865475f)));
                o2 = tf32r(0.5f * o2 * (1.0f + erff(o2 * 0.7071067811865475f)));
                o3 = tf32r(0.5f * o3 * (1.0f + erff(o3 * 0.7071067811865475f)));
            }
            if (OP == 2) {
                const float2 r0 = *(const float2*)(res + (size_t)row * N + col);
                const float2 r1 = *(const float2*)(res + (size_t)(row + 8) * N + col);
                o0 += r0.x; o1 += r0.y; o2 += r1.x; o3 += r1.y;
            }
            *(float2*)(C + (size_t)row * N + col) = make_float2(o0, o1);
            *(float2*)(C + (size_t)(row + 8) * N + col) = make_float2(o2, o3);
        }
    }
}

// ---------------- LayerNorm: one warp per row, float4, no smem ----------------
__global__ void ln_warp_kernel(const float* __restrict__ x, const float* __restrict__ g,
                               const float* __restrict__ bt, float* __restrict__ y,
                               long in_row_stride, int nrows)
{
    const int row = blockIdx.x * 8 + (threadIdx.x >> 5);
    if (row >= nrows) return;
    const int lane = threadIdx.x & 31;
    const float4* xr = (const float4*)(x + (size_t)row * in_row_stride);
    float4 v[3];
    v[0] = xr[lane]; v[1] = xr[lane + 32]; v[2] = xr[lane + 64];
    float s = 0.f, q = 0.f;
#pragma unroll
    for (int t = 0; t < 3; t++) {
        s += v[t].x + v[t].y + v[t].z + v[t].w;
        q += v[t].x * v[t].x + v[t].y * v[t].y + v[t].z * v[t].z + v[t].w * v[t].w;
    }
#pragma unroll
    for (int o = 16; o; o >>= 1) {
        s += __shfl_xor_sync(0xffffffffu, s, o);
        q += __shfl_xor_sync(0xffffffffu, q, o);
    }
    const float mean = s * (1.0f / DD);
    const float rstd = rsqrtf(q * (1.0f / DD) - mean * mean + 1e-5f);
    const float4* gp = (const float4*)g;
    const float4* bp = (const float4*)bt;
    float4* yr = (float4*)(y + (size_t)row * DD);
#pragma unroll
    for (int t = 0; t < 3; t++) {
        float4 gv = gp[lane + 32 * t], bv = bp[lane + 32 * t];
        float4 o;
        o.x = tf32r((v[t].x - mean) * rstd * gv.x + bv.x);
        o.y = tf32r((v[t].y - mean) * rstd * gv.y + bv.y);
        o.z = tf32r((v[t].z - mean) * rstd * gv.z + bv.z);
        o.w = tf32r((v[t].w - mean) * rstd * gv.w + bv.w);
        yr[lane + 32 * t] = o;
    }
}

// ---------------- fused flash attention (3xTF32 tensor cores) ----------------
// grid (2, BH), 256 threads. i-tile 128 rows (warp w: rows wm=16w), j-chunks of 64.
#define FA_SMEM ((2*128 + 4*64 + 2*128) * 68 * 4)   // 208896 B

__global__ void __launch_bounds__(256, 1) flash_attn(const float* __restrict__ qkv,
                                                     float* __restrict__ ctx)
{
    extern __shared__ float sm[];
    float (*Qhi)[68]  = (float(*)[68])sm;        // 128
    float (*Qlo)[68]  = Qhi + 128;
    float (*Khi)[68]  = Qlo + 128;               // 64
    float (*Klo)[68]  = Khi + 64;
    float (*Vthi)[68] = Klo + 64;                // 64 (d) x 64 (j)
    float (*Vtlo)[68] = Vthi + 64;
    float (*Phi)[68]  = Vtlo + 64;               // 128
    float (*Plo)[68]  = Phi + 128;

    const int bh = blockIdx.y;
    const int b = bh / HEADS, h = bh - b * HEADS;
    const int i0 = blockIdx.x * 128;
    const float* base = qkv + (size_t)b * SS * (3 * DD) + h * HD;

    const int tid = threadIdx.x;
    const int lane = tid & 31, warp = tid >> 5;
    const int wm = warp * 16;
    const int r = lane >> 2, cq = lane & 3;
    const bool wactive = (i0 + wm) < SS;

    // load Q (128 x 64), scaled, hi/lo split
    for (int idx = tid; idx < 128 * 16; idx += 256) {
        int ii = idx >> 4, d4 = (idx & 15) * 4;
        int i = i0 + ii;
        float4 v = make_float4(0.f, 0.f, 0.f, 0.f);
        if (i < SS) v = *(const float4*)(base + (size_t)i * (3 * DD) + d4);
        split32(v.x * 0.125f, Qhi[ii][d4 + 0], Qlo[ii][d4 + 0]);
        split32(v.y * 0.125f, Qhi[ii][d4 + 1], Qlo[ii][d4 + 1]);
        split32(v.z * 0.125f, Qhi[ii][d4 + 2], Qlo[ii][d4 + 2]);
        split32(v.w * 0.125f, Qhi[ii][d4 + 3], Qlo[ii][d4 + 3]);
    }

    float o[8][4];
#pragma unroll
    for (int nt = 0; nt < 8; nt++)
#pragma unroll
        for (int i = 0; i < 4; i++) o[nt][i] = 0.f;
    float m0 = -1e30f, m1 = -1e30f, l0 = 0.f, l1 = 0.f;

    for (int jc = 0; jc < 4; jc++) {
        const int jb = jc * 64;
        const int ntmax = (jc < 3) ? 8 : 1;       // chunk widths 64,64,64,5->8
        const int kmax = ntmax * 8;
        __syncthreads();   // previous chunk's PV reads done before K/V overwrite

        // load K chunk (hi/lo)
        for (int idx = tid; idx < 64 * 16; idx += 256) {
            int jj = idx >> 4, d4 = (idx & 15) * 4;
            int j = jb + jj;
            float4 v = make_float4(0.f, 0.f, 0.f, 0.f);
            if (j < SS) v = *(const float4*)(base + (size_t)j * (3 * DD) + DD + d4);
            split32(v.x, Khi[jj][d4 + 0], Klo[jj][d4 + 0]);
            split32(v.y, Khi[jj][d4 + 1], Klo[jj][d4 + 1]);
            split32(v.z, Khi[jj][d4 + 2], Klo[jj][d4 + 2]);
            split32(v.w, Khi[jj][d4 + 3], Klo[jj][d4 + 3]);
        }
        // load V chunk transposed (d x j)
        for (int idx = tid; idx < 64 * 64; idx += 256) {
            int jj = idx >> 6, d = idx & 63;
            int j = jb + jj;
            float v = (j < SS) ? base[(size_t)j * (3 * DD) + 2 * DD + d] : 0.f;
            split32(v, Vthi[d][jj], Vtlo[d][jj]);
        }
        __syncthreads();

        if (wactive) {
            // S = Q K^T (16 x 64 per warp), 3xTF32
            float s[8][4];
#pragma unroll
            for (int nt = 0; nt < 8; nt++)
#pragma unroll
                for (int i = 0; i < 4; i++) s[nt][i] = 0.f;

#pragma unroll
            for (int k0 = 0; k0 < 64; k0 += 8) {
                uint32_t ahi[4], alo[4];
                const float* aph = &Qhi[wm + r][k0 + cq];
                const float* apl = &Qlo[wm + r][k0 + cq];
                ahi[0] = __float_as_uint(aph[0]);          alo[0] = __float_as_uint(apl[0]);
                ahi[1] = __float_as_uint(aph[8 * 68]);     alo[1] = __float_as_uint(apl[8 * 68]);
                ahi[2] = __float_as_uint(aph[4]);          alo[2] = __float_as_uint(apl[4]);
                ahi[3] = __float_as_uint(aph[8 * 68 + 4]); alo[3] = __float_as_uint(apl[8 * 68 + 4]);
                for (int nt = 0; nt < ntmax; nt++) {
                    const float* bph = &Khi[nt * 8 + r][k0 + cq];
                    const float* bpl = &Klo[nt * 8 + r][k0 + cq];
                    uint32_t bhi[2] = {__float_as_uint(bph[0]), __float_as_uint(bph[4])};
                    uint32_t blo[2] = {__float_as_uint(bpl[0]), __float_as_uint(bpl[4])};
                    MMA_TF32(s[nt], ahi, bhi);
                    MMA_TF32(s[nt], ahi, blo);
                    MMA_TF32(s[nt], alo, bhi);
                }
            }

            // mask invalid cols, rowwise max (quad), online softmax update
            float mx0 = -1e30f, mx1 = -1e30f;
            for (int nt = 0; nt < ntmax; nt++) {
                int col = jb + nt * 8 + cq * 2;
                if (col >= SS)     { s[nt][0] = s[nt][2] = -1e30f; }
                if (col + 1 >= SS) { s[nt][1] = s[nt][3] = -1e30f; }
                mx0 = fmaxf(mx0, fmaxf(s[nt][0], s[nt][1]));
                mx1 = fmaxf(mx1, fmaxf(s[nt][2], s[nt][3]));
            }
            mx0 = fmaxf(mx0, __shfl_xor_sync(0xffffffffu, mx0, 1));
            mx0 = fmaxf(mx0, __shfl_xor_sync(0xffffffffu, mx0, 2));
            mx1 = fmaxf(mx1, __shfl_xor_sync(0xffffffffu, mx1, 1));
            mx1 = fmaxf(mx1, __shfl_xor_sync(0xffffffffu, mx1, 2));

            const float mn0 = fmaxf(m0, mx0), mn1 = fmaxf(m1, mx1);
            const float sc0 = expf(m0 - mn0), sc1 = expf(m1 - mn1);
            float sum0 = 0.f, sum1 = 0.f;
            for (int nt = 0; nt < ntmax; nt++) {
                int cc = nt * 8 + cq * 2;
                float p0 = expf(s[nt][0] - mn0);
                float p1 = expf(s[nt][1] - mn0);
                float p2 = expf(s[nt][2] - mn1);
                float p3 = expf(s[nt][3] - mn1);
                sum0 += p0 + p1;
                sum1 += p2 + p3;
                split32(p0, Phi[wm + r][cc],     Plo[wm + r][cc]);
                split32(p1, Phi[wm + r][cc + 1], Plo[wm + r][cc + 1]);
                split32(p2, Phi[wm + r + 8][cc],     Plo[wm + r + 8][cc]);
                split32(p3, Phi[wm + r + 8][cc + 1], Plo[wm + r + 8][cc + 1]);
            }
            sum0 += __shfl_xor_sync(0xffffffffu, sum0, 1);
            sum0 += __shfl_xor_sync(0xffffffffu, sum0, 2);
            sum1 += __shfl_xor_sync(0xffffffffu, sum1, 1);
            sum1 += __shfl_xor_sync(0xffffffffu, sum1, 2);
            l0 = l0 * sc0 + sum0;
            l1 = l1 * sc1 + sum1;
            m0 = mn0; m1 = mn1;
#pragma unroll
            for (int nt = 0; nt < 8; nt++) {
                o[nt][0] *= sc0; o[nt][1] *= sc0;
                o[nt][2] *= sc1; o[nt][3] *= sc1;
            }
            __syncwarp();

            // O += P V  (A = P rows wm.., k = chunk cols; B = V^T d-rows)
            for (int k0 = 0; k0 < kmax; k0 += 8) {
                uint32_t ahi[4], alo[4];
                const float* aph = &Phi[wm + r][k0 + cq];
                const float* apl = &Plo[wm + r][k0 + cq];
                ahi[0] = __float_as_uint(aph[0]);          alo[0] = __float_as_uint(apl[0]);
                ahi[1] = __float_as_uint(aph[8 * 68]);     alo[1] = __float_as_uint(apl[8 * 68]);
                ahi[2] = __float_as_uint(aph[4]);          alo[2] = __float_as_uint(apl[4]);
                ahi[3] = __float_as_uint(aph[8 * 68 + 4]); alo[3] = __float_as_uint(apl[8 * 68 + 4]);
#pragma unroll
                for (int nt = 0; nt < 8; nt++) {
                    const float* bph = &Vthi[nt * 8 + r][k0 + cq];
                    const float* bpl = &Vtlo[nt * 8 + r][k0 + cq];
                    uint32_t bhi[2] = {__float_as_uint(bph[0]), __float_as_uint(bph[4])};
                    uint32_t blo[2] = {__float_as_uint(bpl[0]), __float_as_uint(bpl[4])};
                    MMA_TF32(o[nt], ahi, bhi);
                    MMA_TF32(o[nt], ahi, blo);
                    MMA_TF32(o[nt], alo, bhi);
                }
            }
        }
    }

    if (wactive) {
        const float inv0 = 1.0f / l0, inv1 = 1.0f / l1;
        const int row0 = i0 + wm + r, row1 = row0 + 8;
#pragma unroll
        for (int nt = 0; nt < 8; nt++) {
            const int col = h * HD + nt * 8 + cq * 2;
            if (row0 < SS) {
                float2 ov = make_float2(tf32r(o[nt][0] * inv0), tf32r(o[nt][1] * inv0));
                *(float2*)&ctx[((size_t)b * SS + row0) * DD + col] = ov;
            }
            if (row1 < SS) {
                float2 ov = make_float2(tf32r(o[nt][2] * inv1), tf32r(o[nt][3] * inv1));
                *(float2*)&ctx[((size_t)b * SS + row1) * DD + col] = ov;
            }
        }
    }
}

// ---------------- classifier head ----------------
__global__ void head_kernel(const float* __restrict__ cls, const float* __restrict__ hw,
                            float* __restrict__ out)
{
    __shared__ float s[DD];
    int b = blockIdx.x;
    for (int k = threadIdx.x; k < DD; k += blockDim.x) s[k] = cls[(size_t)b * DD + k];
    __syncthreads();
    int c = threadIdx.x;
    if (c < NCLS) {
        const float* w = hw + (size_t)c * DD;
        float acc = 0.f;
#pragma unroll 8
        for (int k = 0; k < DD; k++) acc += s[k] * w[k];
        out[(size_t)b * NCLS + c] = acc;
    }
}

// ---------------- launch ----------------
extern "C" void kernel_launch(void* const* d_in, const int* in_sizes, int n_in,
                              void* d_out, int out_size) {
    const float* x         = (const float*)d_in[0];
    const float* patch_w   = (const float*)d_in[1];
    const float* patch_b   = (const float*)d_in[2];
    const float* cls_token = (const float*)d_in[3];
    const float* pos_embed = (const float*)d_in[4];
    const float* ln1_g     = (const float*)d_in[5];
    const float* ln1_b     = (const float*)d_in[6];
    const float* qkv_w     = (const float*)d_in[7];
    const float* qkv_b     = (const float*)d_in[8];
    const float* out_w     = (const float*)d_in[9];
    const float* out_b     = (const float*)d_in[10];
    const float* ln2_g     = (const float*)d_in[11];
    const float* ln2_b     = (const float*)d_in[12];
    const float* fc1_w     = (const float*)d_in[13];
    const float* fc1_b     = (const float*)d_in[14];
    const float* fc2_w     = (const float*)d_in[15];
    const float* fc2_b     = (const float*)d_in[16];
    const float* lnf_g     = (const float*)d_in[17];
    const float* lnf_b     = (const float*)d_in[18];
    const float* head_w    = (const float*)d_in[19];
    float* out = (float*)d_out;

    float *patches, *tok, *h, *xn, *qkv, *ctx, *hid, *cls, *w;
    cudaGetSymbolAddress((void**)&patches, g_patches);
    cudaGetSymbolAddress((void**)&tok, g_tok);
    cudaGetSymbolAddress((void**)&h, g_h);
    cudaGetSymbolAddress((void**)&xn, g_xn);
    cudaGetSymbolAddress((void**)&qkv, g_qkv);
    cudaGetSymbolAddress((void**)&ctx, g_ctx);
    cudaGetSymbolAddress((void**)&hid, g_hid);
    cudaGetSymbolAddress((void**)&cls, g_cls);
    cudaGetSymbolAddress((void**)&w, g_w);

    cudaFuncSetAttribute(gemm_tf32<0>, cudaFuncAttributeMaxDynamicSharedMemorySize, GEMM_SMEM);
    cudaFuncSetAttribute(gemm_tf32<1>, cudaFuncAttributeMaxDynamicSharedMemorySize, GEMM_SMEM);
    cudaFuncSetAttribute(gemm_tf32<2>, cudaFuncAttributeMaxDynamicSharedMemorySize, GEMM_SMEM);
    cudaFuncSetAttribute(flash_attn, cudaFuncAttributeMaxDynamicSharedMemorySize, FA_SMEM);

    round_all_kernel<<<(W_TOTAL / 4 + 255) / 256, 256>>>(patch_w, qkv_w, out_w, fc1_w, fc2_w, w);
    patchify_kernel<<<(PTOK * PATCH_DIM + 255) / 256, 256>>>(x, patches);
    gemm_tf32<0><<<dim3(DD / 128, PTOK / 128), 256, GEMM_SMEM>>>(
        patches, w + W_PATCH, patch_b, nullptr, tok, PTOK, DD, PATCH_DIM);
    assemble_kernel<<<(TOK * DD + 255) / 256, 256>>>(tok, cls_token, pos_embed, h);

    for (int i = 0; i < DEPTH; i++) {
        ln_warp_kernel<<<(TOK + 7) / 8, 256>>>(h, ln1_g + i * DD, ln1_b + i * DD, xn, DD, TOK);
        gemm_tf32<0><<<dim3(3 * DD / 128, TOK / 128), 256, GEMM_SMEM>>>(
            xn, w + W_QKV + (size_t)i * 3 * DD * DD, qkv_b + (size_t)i * 3 * DD,
            nullptr, qkv, TOK, 3 * DD, DD);
        flash_attn<<<dim3(2, BH), 256, FA_SMEM>>>(qkv, ctx);
        gemm_tf32<2><<<dim3(DD / 128, TOK / 128), 256, GEMM_SMEM>>>(
            ctx, w + W_OUT + (size_t)i * DD * DD, out_b + (size_t)i * DD, h, h, TOK, DD, DD);
        ln_warp_kernel<<<(TOK + 7) / 8, 256>>>(h, ln2_g + i * DD, ln2_b + i * DD, xn, DD, TOK);
        gemm_tf32<1><<<dim3(HID / 128, TOK / 128), 256, GEMM_SMEM>>>(
            xn, w + W_FC1 + (size_t)i * HID * DD, fc1_b + (size_t)i * HID,
            nullptr, hid, TOK, HID, DD);
        gemm_tf32<2><<<dim3(DD / 128, TOK / 128), 256, GEMM_SMEM>>>(
            hid, w + W_FC2 + (size_t)i * DD * HID, fc2_b + (size_t)i * DD, h, h, TOK, DD, HID);
    }

    ln_warp_kernel<<<(BB + 7) / 8, 256>>>(h, lnf_g, lnf_b, cls, (long)SS * DD, BB);
    head_kernel<<<BB, 128>>>(cls, head_w, out);
}

// round 6
// speedup vs baseline: 1.3522x; 1.1563x over previous
#include <cuda_runtime.h>
#include <math.h>
#include <stdint.h>

// ---------------- problem constants ----------------
#define BB 128
#define CC 3
#define IMG 224
#define PP 16
#define HP 14
#define NP 196
#define SS 197
#define DD 384
#define HEADS 6
#define HD 64
#define DEPTH 12
#define HID 1536
#define NCLS 100
#define PATCH_DIM 768
#define TOK (BB*SS)    // 25216
#define PTOK (BB*NP)   // 25088
#define BH (BB*HEADS)  // 768

// ---------------- scratch ----------------
__device__ float g_patches[PTOK * PATCH_DIM];
__device__ float g_tok[PTOK * DD];
__device__ float g_h[TOK * DD];
__device__ float g_xn[TOK * DD];
__device__ float g_qkv[TOK * 3 * DD];
__device__ float g_ctx[TOK * DD];
__device__ float g_hid[TOK * HID];
__device__ float g_cls[BB * DD];
// tf32-rounded weights (offsets in floats)
#define W_PATCH 0
#define W_QKV   294912
#define W_OUT   5603328
#define W_FC1   7372800
#define W_FC2   14450688
#define W_TOTAL 21528576
__device__ float g_w[W_TOTAL];

// ---------------- helpers ----------------
__device__ __forceinline__ float tf32r(float x) {
    uint32_t u;
    asm("cvt.rna.tf32.f32 %0, %1;" : "=r"(u) : "f"(x));
    return __uint_as_float(u);
}
// split fp32 -> (hi, lo) tf32 bit patterns as uints
__device__ __forceinline__ void split_u(float x, uint32_t& hi, uint32_t& lo) {
    float h = tf32r(x);
    hi = __float_as_uint(h);
    lo = __float_as_uint(tf32r(x - h));
}
__device__ __forceinline__ uint32_t smem_u32(const void* p) {
    return (uint32_t)__cvta_generic_to_shared(p);
}
#define CPA(dst, src) asm volatile("cp.async.cg.shared.global [%0], [%1], 16;" :: "r"(dst), "l"(src))
#define CPC() asm volatile("cp.async.commit_group;")
#define CPW0() asm volatile("cp.async.wait_group 0;")
#define CPW1() asm volatile("cp.async.wait_group 1;")
#define MMA_TF32(d, a, b) asm volatile( \
    "mma.sync.aligned.m16n8k8.row.col.f32.tf32.tf32.f32 " \
    "{%0,%1,%2,%3},{%4,%5,%6,%7},{%8,%9},{%0,%1,%2,%3};" \
    : "+f"(d[0]), "+f"(d[1]), "+f"(d[2]), "+f"(d[3]) \
    : "r"(a[0]), "r"(a[1]), "r"(a[2]), "r"(a[3]), "r"(b[0]), "r"(b[1]))

// ---------------- weight rounding, split into 2 launches (profiler indexing) ----------------
__global__ void round_w_a(const float* __restrict__ pw, const float* __restrict__ qw,
                          const float* __restrict__ ow, float* __restrict__ w) {
    int i = blockIdx.x * blockDim.x + threadIdx.x;
    if (i >= W_FC1 / 4) return;
    int f = i * 4;
    const float* src; int off;
    if (f < W_QKV)      { src = pw; off = f - W_PATCH; }
    else if (f < W_OUT) { src = qw; off = f - W_QKV; }
    else                { src = ow; off = f - W_OUT; }
    float4 v = *(const float4*)(src + off);
    v.x = tf32r(v.x); v.y = tf32r(v.y); v.z = tf32r(v.z); v.w = tf32r(v.w);
    ((float4*)w)[i] = v;
}
__global__ void round_w_b(const float* __restrict__ f1, const float* __restrict__ f2,
                          float* __restrict__ w) {
    int i = blockIdx.x * blockDim.x + threadIdx.x;
    if (i >= (W_TOTAL - W_FC1) / 4) return;
    int f = W_FC1 + i * 4;
    const float* src; int off;
    if (f < W_FC2) { src = f1; off = f - W_FC1; }
    else           { src = f2; off = f - W_FC2; }
    float4 v = *(const float4*)(src + off);
    v.x = tf32r(v.x); v.y = tf32r(v.y); v.z = tf32r(v.z); v.w = tf32r(v.w);
    ((float4*)(w + W_FC1))[i] = v;
}

// ---------------- patchify (+tf32 round) ----------------
__global__ void patchify_kernel(const float* __restrict__ x, float* __restrict__ patches) {
    int idx = blockIdx.x * blockDim.x + threadIdx.x;
    if (idx >= PTOK * PATCH_DIM) return;
    int t = idx / PATCH_DIM;
    int k = idx - t * PATCH_DIM;
    int b = t / NP;
    int n = t - b * NP;
    int ph = n / HP, pw = n - ph * HP;
    int c = k >> 8;
    int py = (k >> 4) & 15;
    int px = k & 15;
    patches[idx] = tf32r(x[(((size_t)b * CC + c) * IMG + (ph * PP + py)) * IMG + (pw * PP + px)]);
}

// ---------------- assemble h = [cls; tok] + pos ----------------
__global__ void assemble_kernel(const float* __restrict__ tok, const float* __restrict__ cls_token,
                                const float* __restrict__ pos, float* __restrict__ h) {
    int idx = blockIdx.x * blockDim.x + threadIdx.x;
    if (idx >= TOK * DD) return;
    int row = idx / DD;
    int d = idx - row * DD;
    int b = row / SS;
    int s = row - b * SS;
    float v = (s == 0) ? cls_token[d] : tok[((size_t)b * NP + (s - 1)) * DD + d];
    h[idx] = v + pos[s * DD + d];
}

// ---------------- tf32 tensor-core NT GEMM, BK=32, 2-stage cp.async ----------------
#define GBK 32
#define GST 36
#define GEMM_SMEM (2 * 2 * 128 * GST * 4)   // 73728 B

template <int OP>
__global__ void __launch_bounds__(256, 2) gemm_tf32(
    const float* __restrict__ A, const float* __restrict__ Bw,
    const float* __restrict__ bias, const float* __restrict__ res,
    float* __restrict__ C, int M, int N, int K)
{
    extern __shared__ float gsm[];
    float* As = gsm;                   // [2][128][GST]
    float* Bs = gsm + 2 * 128 * GST;

    const int tid = threadIdx.x;
    const int lane = tid & 31, warp = tid >> 5;
    const int wm = (warp >> 1) * 32;
    const int wn = (warp & 1) * 64;
    const int r = lane >> 2, cq = lane & 3;
    const int m0 = blockIdx.y * 128, n0 = blockIdx.x * 128;

    const int lr = tid >> 3;           // 0..31
    const int lc = (tid & 7) * 4;      // 0..28
    const float* Ag = A + (size_t)(m0 + lr) * K + lc;
    const float* Bg = Bw + (size_t)(n0 + lr) * K + lc;
    uint32_t sA[2][4], sB[2][4];
#pragma unroll
    for (int s = 0; s < 2; s++)
#pragma unroll
        for (int c = 0; c < 4; c++) {
            sA[s][c] = smem_u32(As + (size_t)(s * 128 + lr + c * 32) * GST + lc);
            sB[s][c] = smem_u32(Bs + (size_t)(s * 128 + lr + c * 32) * GST + lc);
        }

    float acc[2][8][4];
#pragma unroll
    for (int mt = 0; mt < 2; mt++)
#pragma unroll
        for (int nt = 0; nt < 8; nt++)
#pragma unroll
            for (int i = 0; i < 4; i++) acc[mt][nt][i] = 0.f;

    const int KT = K / GBK;
#pragma unroll
    for (int c = 0; c < 4; c++) {
        CPA(sA[0][c], Ag + (size_t)c * 32 * K);
        CPA(sB[0][c], Bg + (size_t)c * 32 * K);
    }
    CPC();

    for (int kt = 0; kt < KT; kt++) {
        const int buf = kt & 1;
        if (kt + 1 < KT) {
            const int nb = buf ^ 1;
            const int ko = (kt + 1) * GBK;
#pragma unroll
            for (int c = 0; c < 4; c++) {
                CPA(sA[nb][c], Ag + (size_t)c * 32 * K + ko);
                CPA(sB[nb][c], Bg + (size_t)c * 32 * K + ko);
            }
            CPC();
            CPW1();
        } else {
            CPW0();
        }
        __syncthreads();

#pragma unroll
        for (int ks = 0; ks < 4; ks++) {
            const int k0 = ks * 8;
            uint32_t a[2][4], b[8][2];
#pragma unroll
            for (int mt = 0; mt < 2; mt++) {
                const float* ap = As + (size_t)(buf * 128 + wm + mt * 16 + r) * GST + k0 + cq;
                a[mt][0] = __float_as_uint(ap[0]);
                a[mt][1] = __float_as_uint(ap[8 * GST]);
                a[mt][2] = __float_as_uint(ap[4]);
                a[mt][3] = __float_as_uint(ap[8 * GST + 4]);
            }
#pragma unroll
            for (int nt = 0; nt < 8; nt++) {
                const float* bp = Bs + (size_t)(buf * 128 + wn + nt * 8 + r) * GST + k0 + cq;
                b[nt][0] = __float_as_uint(bp[0]);
                b[nt][1] = __float_as_uint(bp[4]);
            }
#pragma unroll
            for (int mt = 0; mt < 2; mt++)
#pragma unroll
                for (int nt = 0; nt < 8; nt++)
                    MMA_TF32(acc[mt][nt], a[mt], b[nt]);
        }
        __syncthreads();
    }

#pragma unroll
    for (int mt = 0; mt < 2; mt++) {
        const int row = m0 + wm + mt * 16 + r;
#pragma unroll
        for (int nt = 0; nt < 8; nt++) {
            const int col = n0 + wn + nt * 8 + cq * 2;
            const float2 bv = *(const float2*)(bias + col);
            float o0 = acc[mt][nt][0] + bv.x;
            float o1 = acc[mt][nt][1] + bv.y;
            float o2 = acc[mt][nt][2] + bv.x;
            float o3 = acc[mt][nt][3] + bv.y;
            if (OP == 1) {
                o0 = tf32r(0.5f * o0 * (1.0f + erff(o0 * 0.7071067811865475f)));
                o1 = tf32r(0.5f * o1 * (1.0f + erff(o1 * 0.7071067811865475f)));
                o2 = tf32r(0.5f * o2 * (1.0f + erff(o2 * 0.7071067811865475f)));
                o3 = tf32r(0.5f * o3 * (1.0f + erff(o3 * 0.7071067811865475f)));
            }
            if (OP == 2) {
                const float2 r0 = *(const float2*)(res + (size_t)row * N + col);
                const float2 r1 = *(const float2*)(res + (size_t)(row + 8) * N + col);
                o0 += r0.x; o1 += r0.y; o2 += r1.x; o3 += r1.y;
            }
            *(float2*)(C + (size_t)row * N + col) = make_float2(o0, o1);
            *(float2*)(C + (size_t)(row + 8) * N + col) = make_float2(o2, o3);
        }
    }
}

// ---------------- LayerNorm: one warp per row ----------------
__global__ void ln_warp_kernel(const float* __restrict__ x, const float* __restrict__ g,
                               const float* __restrict__ bt, float* __restrict__ y,
                               long in_row_stride, int nrows)
{
    const int row = blockIdx.x * 8 + (threadIdx.x >> 5);
    if (row >= nrows) return;
    const int lane = threadIdx.x & 31;
    const float4* xr = (const float4*)(x + (size_t)row * in_row_stride);
    float4 v[3];
    v[0] = xr[lane]; v[1] = xr[lane + 32]; v[2] = xr[lane + 64];
    float s = 0.f, q = 0.f;
#pragma unroll
    for (int t = 0; t < 3; t++) {
        s += v[t].x + v[t].y + v[t].z + v[t].w;
        q += v[t].x * v[t].x + v[t].y * v[t].y + v[t].z * v[t].z + v[t].w * v[t].w;
    }
#pragma unroll
    for (int o = 16; o; o >>= 1) {
        s += __shfl_xor_sync(0xffffffffu, s, o);
        q += __shfl_xor_sync(0xffffffffu, q, o);
    }
    const float mean = s * (1.0f / DD);
    const float rstd = rsqrtf(q * (1.0f / DD) - mean * mean + 1e-5f);
    const float4* gp = (const float4*)g;
    const float4* bp = (const float4*)bt;
    float4* yr = (float4*)(y + (size_t)row * DD);
#pragma unroll
    for (int t = 0; t < 3; t++) {
        float4 gv = gp[lane + 32 * t], bv = bp[lane + 32 * t];
        float4 o;
        o.x = tf32r((v[t].x - mean) * rstd * gv.x + bv.x);
        o.y = tf32r((v[t].y - mean) * rstd * gv.y + bv.y);
        o.z = tf32r((v[t].z - mean) * rstd * gv.z + bv.z);
        o.w = tf32r((v[t].w - mean) * rstd * gv.w + bv.w);
        yr[lane + 32 * t] = o;
    }
}

// ---------------- fused flash attention, fp32 smem + split-at-use 3xTF32 ----------------
// smem: Q[128][68] + K[64][68] + Vt[64][68] + P[128][68] fp32 = 104448 B -> 2 blocks/SM
#define FA_SMEM ((128 + 64 + 64 + 128) * 68 * 4)

__global__ void __launch_bounds__(256, 2) flash_attn(const float* __restrict__ qkv,
                                                     float* __restrict__ ctx)
{
    extern __shared__ float sm[];
    float (*Qs)[68] = (float(*)[68])sm;     // 128 rows (pre-scaled)
    float (*Ks)[68] = Qs + 128;             // 64 rows (j x d)
    float (*Vt)[68] = Ks + 64;              // 64 rows (d x j)
    float (*Ps)[68] = Vt + 64;              // 128 rows (i x j)

    const int bh = blockIdx.y;
    const int b = bh / HEADS, h = bh - b * HEADS;
    const int i0 = blockIdx.x * 128;
    const float* base = qkv + (size_t)b * SS * (3 * DD) + h * HD;

    const int tid = threadIdx.x;
    const int lane = tid & 31, warp = tid >> 5;
    const int wm = warp * 16;               // warp owns rows wm..wm+15
    const int r = lane >> 2, cq = lane & 3;
    const bool wactive = (i0 + wm) < SS;

    // load Q (128 x 64), scaled, fp32
    for (int idx = tid; idx < 128 * 16; idx += 256) {
        int ii = idx >> 4, d4 = (idx & 15) * 4;
        int i = i0 + ii;
        float4 v = make_float4(0.f, 0.f, 0.f, 0.f);
        if (i < SS) v = *(const float4*)(base + (size_t)i * (3 * DD) + d4);
        Qs[ii][d4 + 0] = v.x * 0.125f;
        Qs[ii][d4 + 1] = v.y * 0.125f;
        Qs[ii][d4 + 2] = v.z * 0.125f;
        Qs[ii][d4 + 3] = v.w * 0.125f;
    }

    float o[8][4];
#pragma unroll
    for (int nt = 0; nt < 8; nt++)
#pragma unroll
        for (int i = 0; i < 4; i++) o[nt][i] = 0.f;
    float m0 = -1e30f, m1 = -1e30f, l0 = 0.f, l1 = 0.f;

    for (int jc = 0; jc < 4; jc++) {
        const int jb = jc * 64;
        const int ntmax = (jc < 3) ? 8 : 1;     // last chunk: cols 192..199 (5 valid)
        __syncthreads();                        // previous chunk fully consumed

        // load K chunk (j x d) fp32
        for (int idx = tid; idx < 64 * 16; idx += 256) {
            int jj = idx >> 4, d4 = (idx & 15) * 4;
            int j = jb + jj;
            float4 v = make_float4(0.f, 0.f, 0.f, 0.f);
            if (j < SS) v = *(const float4*)(base + (size_t)j * (3 * DD) + DD + d4);
            Ks[jj][d4 + 0] = v.x; Ks[jj][d4 + 1] = v.y;
            Ks[jj][d4 + 2] = v.z; Ks[jj][d4 + 3] = v.w;
        }
        // load V chunk transposed (d x j) fp32
        for (int idx = tid; idx < 64 * 16; idx += 256) {
            int jj = idx >> 4, d4 = (idx & 15) * 4;
            int j = jb + jj;
            float4 v = make_float4(0.f, 0.f, 0.f, 0.f);
            if (j < SS) v = *(const float4*)(base + (size_t)j * (3 * DD) + 2 * DD + d4);
            Vt[d4 + 0][jj] = v.x; Vt[d4 + 1][jj] = v.y;
            Vt[d4 + 2][jj] = v.z; Vt[d4 + 3][jj] = v.w;
        }
        __syncthreads();

        if (wactive) {
            // ---- S = Q K^T (16 x 64 per warp), split-at-use 3xTF32 ----
            float s[8][4];
#pragma unroll
            for (int nt = 0; nt < 8; nt++)
#pragma unroll
                for (int i = 0; i < 4; i++) s[nt][i] = 0.f;

#pragma unroll
            for (int k0 = 0; k0 < 64; k0 += 8) {
                uint32_t ahi[4], alo[4];
                split_u(Qs[wm + r][k0 + cq],         ahi[0], alo[0]);
                split_u(Qs[wm + r + 8][k0 + cq],     ahi[1], alo[1]);
                split_u(Qs[wm + r][k0 + cq + 4],     ahi[2], alo[2]);
                split_u(Qs[wm + r + 8][k0 + cq + 4], ahi[3], alo[3]);
                for (int nt = 0; nt < ntmax; nt++) {
                    uint32_t bhi[2], blo[2];
                    split_u(Ks[nt * 8 + r][k0 + cq],     bhi[0], blo[0]);
                    split_u(Ks[nt * 8 + r][k0 + cq + 4], bhi[1], blo[1]);
                    MMA_TF32(s[nt], ahi, bhi);
                    MMA_TF32(s[nt], ahi, blo);
                    MMA_TF32(s[nt], alo, bhi);
                }
            }

            // ---- mask, rowwise max (quad), online softmax ----
            float mx0 = -1e30f, mx1 = -1e30f;
            for (int nt = 0; nt < ntmax; nt++) {
                int col = jb + nt * 8 + cq * 2;
                if (col >= SS)     { s[nt][0] = s[nt][2] = -1e30f; }
                if (col + 1 >= SS) { s[nt][1] = s[nt][3] = -1e30f; }
                mx0 = fmaxf(mx0, fmaxf(s[nt][0], s[nt][1]));
                mx1 = fmaxf(mx1, fmaxf(s[nt][2], s[nt][3]));
            }
            mx0 = fmaxf(mx0, __shfl_xor_sync(0xffffffffu, mx0, 1));
            mx0 = fmaxf(mx0, __shfl_xor_sync(0xffffffffu, mx0, 2));
            mx1 = fmaxf(mx1, __shfl_xor_sync(0xffffffffu, mx1, 1));
            mx1 = fmaxf(mx1, __shfl_xor_sync(0xffffffffu, mx1, 2));

            const float mn0 = fmaxf(m0, mx0), mn1 = fmaxf(m1, mx1);
            const float sc0 = expf(m0 - mn0), sc1 = expf(m1 - mn1);
            float sum0 = 0.f, sum1 = 0.f;
            for (int nt = 0; nt < ntmax; nt++) {
                int cc = nt * 8 + cq * 2;
                float p0 = expf(s[nt][0] - mn0);
                float p1 = expf(s[nt][1] - mn0);
                float p2 = expf(s[nt][2] - mn1);
                float p3 = expf(s[nt][3] - mn1);
                sum0 += p0 + p1;
                sum1 += p2 + p3;
                Ps[wm + r][cc] = p0;     Ps[wm + r][cc + 1] = p1;
                Ps[wm + r + 8][cc] = p2; Ps[wm + r + 8][cc + 1] = p3;
            }
            sum0 += __shfl_xor_sync(0xffffffffu, sum0, 1);
            sum0 += __shfl_xor_sync(0xffffffffu, sum0, 2);
            sum1 += __shfl_xor_sync(0xffffffffu, sum1, 1);
            sum1 += __shfl_xor_sync(0xffffffffu, sum1, 2);
            l0 = l0 * sc0 + sum0;
            l1 = l1 * sc1 + sum1;
            m0 = mn0; m1 = mn1;
#pragma unroll
            for (int nt = 0; nt < 8; nt++) {
                o[nt][0] *= sc0; o[nt][1] *= sc0;
                o[nt][2] *= sc1; o[nt][3] *= sc1;
            }
            __syncwarp();   // P writes visible to whole warp

            // ---- O += P V (A = own P rows, B = Vt d-rows), split-at-use ----
            for (int k0 = 0; k0 < ntmax * 8; k0 += 8) {
                uint32_t ahi[4], alo[4];
                split_u(Ps[wm + r][k0 + cq],         ahi[0], alo[0]);
                split_u(Ps[wm + r + 8][k0 + cq],     ahi[1], alo[1]);
                split_u(Ps[wm + r][k0 + cq + 4],     ahi[2], alo[2]);
                split_u(Ps[wm + r + 8][k0 + cq + 4], ahi[3], alo[3]);
#pragma unroll
                for (int nt = 0; nt < 8; nt++) {
                    uint32_t bhi[2], blo[2];
                    split_u(Vt[nt * 8 + r][k0 + cq],     bhi[0], blo[0]);
                    split_u(Vt[nt * 8 + r][k0 + cq + 4], bhi[1], blo[1]);
                    MMA_TF32(o[nt], ahi, bhi);
                    MMA_TF32(o[nt], ahi, blo);
                    MMA_TF32(o[nt], alo, bhi);
                }
            }
        }
    }

    if (wactive) {
        const float inv0 = 1.0f / l0, inv1 = 1.0f / l1;
        const int row0 = i0 + wm + r, row1 = row0 + 8;
#pragma unroll
        for (int nt = 0; nt < 8; nt++) {
            const int col = h * HD + nt * 8 + cq * 2;
            if (row0 < SS) {
                float2 ov = make_float2(tf32r(o[nt][0] * inv0), tf32r(o[nt][1] * inv0));
                *(float2*)&ctx[((size_t)b * SS + row0) * DD + col] = ov;
            }
            if (row1 < SS) {
                float2 ov = make_float2(tf32r(o[nt][2] * inv1), tf32r(o[nt][3] * inv1));
                *(float2*)&ctx[((size_t)b * SS + row1) * DD + col] = ov;
            }
        }
    }
}

// ---------------- classifier head ----------------
__global__ void head_kernel(const float* __restrict__ cls, const float* __restrict__ hw,
                            float* __restrict__ out)
{
    __shared__ float s[DD];
    int b = blockIdx.x;
    for (int k = threadIdx.x; k < DD; k += blockDim.x) s[k] = cls[(size_t)b * DD + k];
    __syncthreads();
    int c = threadIdx.x;
    if (c < NCLS) {
        const float* w = hw + (size_t)c * DD;
        float acc = 0.f;
#pragma unroll 8
        for (int k = 0; k < DD; k++) acc += s[k] * w[k];
        out[(size_t)b * NCLS + c] = acc;
    }
}

// ---------------- launch ----------------
extern "C" void kernel_launch(void* const* d_in, const int* in_sizes, int n_in,
                              void* d_out, int out_size) {
    const float* x         = (const float*)d_in[0];
    const float* patch_w   = (const float*)d_in[1];
    const float* patch_b   = (const float*)d_in[2];
    const float* cls_token = (const float*)d_in[3];
    const float* pos_embed = (const float*)d_in[4];
    const float* ln1_g     = (const float*)d_in[5];
    const float* ln1_b     = (const float*)d_in[6];
    const float* qkv_w     = (const float*)d_in[7];
    const float* qkv_b     = (const float*)d_in[8];
    const float* out_w     = (const float*)d_in[9];
    const float* out_b     = (const float*)d_in[10];
    const float* ln2_g     = (const float*)d_in[11];
    const float* ln2_b     = (const float*)d_in[12];
    const float* fc1_w     = (const float*)d_in[13];
    const float* fc1_b     = (const float*)d_in[14];
    const float* fc2_w     = (const float*)d_in[15];
    const float* fc2_b     = (const float*)d_in[16];
    const float* lnf_g     = (const float*)d_in[17];
    const float* lnf_b     = (const float*)d_in[18];
    const float* head_w    = (const float*)d_in[19];
    float* out = (float*)d_out;

    float *patches, *tok, *h, *xn, *qkv, *ctx, *hid, *cls, *w;
    cudaGetSymbolAddress((void**)&patches, g_patches);
    cudaGetSymbolAddress((void**)&tok, g_tok);
    cudaGetSymbolAddress((void**)&h, g_h);
    cudaGetSymbolAddress((void**)&xn, g_xn);
    cudaGetSymbolAddress((void**)&qkv, g_qkv);
    cudaGetSymbolAddress((void**)&ctx, g_ctx);
    cudaGetSymbolAddress((void**)&hid, g_hid);
    cudaGetSymbolAddress((void**)&cls, g_cls);
    cudaGetSymbolAddress((void**)&w, g_w);

    cudaFuncSetAttribute(gemm_tf32<0>, cudaFuncAttributeMaxDynamicSharedMemorySize, GEMM_SMEM);
    cudaFuncSetAttribute(gemm_tf32<1>, cudaFuncAttributeMaxDynamicSharedMemorySize, GEMM_SMEM);
    cudaFuncSetAttribute(gemm_tf32<2>, cudaFuncAttributeMaxDynamicSharedMemorySize, GEMM_SMEM);
    cudaFuncSetAttribute(flash_attn, cudaFuncAttributeMaxDynamicSharedMemorySize, FA_SMEM);

    // 0,1: weight rounding; 2: patchify; 3: patch GEMM (profiled index)
    round_w_a<<<(W_FC1 / 4 + 255) / 256, 256>>>(patch_w, qkv_w, out_w, w);
    round_w_b<<<((W_TOTAL - W_FC1) / 4 + 255) / 256, 256>>>(fc1_w, fc2_w, w);
    patchify_kernel<<<(PTOK * PATCH_DIM + 255) / 256, 256>>>(x, patches);
    gemm_tf32<0><<<dim3(DD / 128, PTOK / 128), 256, GEMM_SMEM>>>(
        patches, w + W_PATCH, patch_b, nullptr, tok, PTOK, DD, PATCH_DIM);
    assemble_kernel<<<(TOK * DD + 255) / 256, 256>>>(tok, cls_token, pos_embed, h);

    for (int i = 0; i < DEPTH; i++) {
        ln_warp_kernel<<<(TOK + 7) / 8, 256>>>(h, ln1_g + i * DD, ln1_b + i * DD, xn, DD, TOK);
        gemm_tf32<0><<<dim3(3 * DD / 128, TOK / 128), 256, GEMM_SMEM>>>(
            xn, w + W_QKV + (size_t)i * 3 * DD * DD, qkv_b + (size_t)i * 3 * DD,
            nullptr, qkv, TOK, 3 * DD, DD);
        flash_attn<<<dim3(2, BH), 256, FA_SMEM>>>(qkv, ctx);
        gemm_tf32<2><<<dim3(DD / 128, TOK / 128), 256, GEMM_SMEM>>>(
            ctx, w + W_OUT + (size_t)i * DD * DD, out_b + (size_t)i * DD, h, h, TOK, DD, DD);
        ln_warp_kernel<<<(TOK + 7) / 8, 256>>>(h, ln2_g + i * DD, ln2_b + i * DD, xn, DD, TOK);
        gemm_tf32<1><<<dim3(HID / 128, TOK / 128), 256, GEMM_SMEM>>>(
            xn, w + W_FC1 + (size_t)i * HID * DD, fc1_b + (size_t)i * HID,
            nullptr, hid, TOK, HID, DD);
        gemm_tf32<2><<<dim3(DD / 128, TOK / 128), 256, GEMM_SMEM>>>(
            hid, w + W_FC2 + (size_t)i * DD * HID, fc2_b + (size_t)i * DD, h, h, TOK, DD, HID);
    }

    ln_warp_kernel<<<(BB + 7) / 8, 256>>>(h, lnf_g, lnf_b, cls, (long)SS * DD, BB);
    head_kernel<<<BB, 128>>>(cls, head_w, out);
}

// round 7
// speedup vs baseline: 1.4433x; 1.0674x over previous
#include <cuda_runtime.h>
#include <math.h>
#include <stdint.h>

// ---------------- problem constants ----------------
#define BB 128
#define CC 3
#define IMG 224
#define PP 16
#define HP 14
#define NP 196
#define SS 197
#define DD 384
#define HEADS 6
#define HD 64
#define DEPTH 12
#define HID 1536
#define NCLS 100
#define PATCH_DIM 768
#define TOK (BB*SS)    // 25216
#define PTOK (BB*NP)   // 25088
#define BH (BB*HEADS)  // 768

// ---------------- scratch ----------------
__device__ float g_patches[PTOK * PATCH_DIM];
__device__ float g_tok[PTOK * DD];
__device__ float g_h[TOK * DD];
__device__ float g_xn[TOK * DD];
__device__ float g_qkv[TOK * 3 * DD];
__device__ float g_ctx[TOK * DD];
__device__ float g_hid[TOK * HID];
__device__ float g_cls[BB * DD];
// tf32-rounded weights (offsets in floats)
#define W_PATCH 0
#define W_QKV   294912
#define W_OUT   5603328
#define W_FC1   7372800
#define W_FC2   14450688
#define W_TOTAL 21528576
__device__ float g_w[W_TOTAL];

// ---------------- helpers ----------------
__device__ __forceinline__ float tf32r(float x) {
    uint32_t u;
    asm("cvt.rna.tf32.f32 %0, %1;" : "=r"(u) : "f"(x));
    return __uint_as_float(u);
}
__device__ __forceinline__ void split_u(float x, uint32_t& hi, uint32_t& lo) {
    float h = tf32r(x);
    hi = __float_as_uint(h);
    lo = __float_as_uint(tf32r(x - h));
}
__device__ __forceinline__ uint32_t smem_u32(const void* p) {
    return (uint32_t)__cvta_generic_to_shared(p);
}
#define CPA(dst, src) asm volatile("cp.async.cg.shared.global [%0], [%1], 16;" :: "r"(dst), "l"(src))
#define CPC() asm volatile("cp.async.commit_group;")
#define CPW0() asm volatile("cp.async.wait_group 0;")
#define CPW1() asm volatile("cp.async.wait_group 1;")
#define MMA_TF32(d, a, b) asm volatile( \
    "mma.sync.aligned.m16n8k8.row.col.f32.tf32.tf32.f32 " \
    "{%0,%1,%2,%3},{%4,%5,%6,%7},{%8,%9},{%0,%1,%2,%3};" \
    : "+f"(d[0]), "+f"(d[1]), "+f"(d[2]), "+f"(d[3]) \
    : "r"(a[0]), "r"(a[1]), "r"(a[2]), "r"(a[3]), "r"(b[0]), "r"(b[1]))

// ---------------- weight rounding, split into 2 launches (profiler indexing) ----------------
__global__ void round_w_a(const float* __restrict__ pw, const float* __restrict__ qw,
                          const float* __restrict__ ow, float* __restrict__ w) {
    int i = blockIdx.x * blockDim.x + threadIdx.x;
    if (i >= W_FC1 / 4) return;
    int f = i * 4;
    const float* src; int off;
    if (f < W_QKV)      { src = pw; off = f - W_PATCH; }
    else if (f < W_OUT) { src = qw; off = f - W_QKV; }
    else                { src = ow; off = f - W_OUT; }
    float4 v = *(const float4*)(src + off);
    v.x = tf32r(v.x); v.y = tf32r(v.y); v.z = tf32r(v.z); v.w = tf32r(v.w);
    ((float4*)w)[i] = v;
}
__global__ void round_w_b(const float* __restrict__ f1, const float* __restrict__ f2,
                          float* __restrict__ w) {
    int i = blockIdx.x * blockDim.x + threadIdx.x;
    if (i >= (W_TOTAL - W_FC1) / 4) return;
    int f = W_FC1 + i * 4;
    const float* src; int off;
    if (f < W_FC2) { src = f1; off = f - W_FC1; }
    else           { src = f2; off = f - W_FC2; }
    float4 v = *(const float4*)(src + off);
    v.x = tf32r(v.x); v.y = tf32r(v.y); v.z = tf32r(v.z); v.w = tf32r(v.w);
    ((float4*)(w + W_FC1))[i] = v;
}

// ---------------- patchify (+tf32 round) ----------------
__global__ void patchify_kernel(const float* __restrict__ x, float* __restrict__ patches) {
    int idx = blockIdx.x * blockDim.x + threadIdx.x;
    if (idx >= PTOK * PATCH_DIM) return;
    int t = idx / PATCH_DIM;
    int k = idx - t * PATCH_DIM;
    int b = t / NP;
    int n = t - b * NP;
    int ph = n / HP, pw = n - ph * HP;
    int c = k >> 8;
    int py = (k >> 4) & 15;
    int px = k & 15;
    patches[idx] = tf32r(x[(((size_t)b * CC + c) * IMG + (ph * PP + py)) * IMG + (pw * PP + px)]);
}

// ---------------- assemble h = [cls; tok] + pos ----------------
__global__ void assemble_kernel(const float* __restrict__ tok, const float* __restrict__ cls_token,
                                const float* __restrict__ pos, float* __restrict__ h) {
    int idx = blockIdx.x * blockDim.x + threadIdx.x;
    if (idx >= TOK * DD) return;
    int row = idx / DD;
    int d = idx - row * DD;
    int b = row / SS;
    int s = row - b * SS;
    float v = (s == 0) ? cls_token[d] : tok[((size_t)b * NP + (s - 1)) * DD + d];
    h[idx] = v + pos[s * DD + d];
}

// ---------------- tf32 NT GEMM: swizzled smem, 3-stage cp.async, 1 barrier/iter ----------------
// smem stage: 128 rows x 32 floats (A and B). element (row,k) at col k ^ (4*(row&7)).
#define GSTAGE 4096                         // floats per stage per operand
#define GEMM_SMEM (3 * 2 * GSTAGE * 4)      // 98304 B

template <int OP>
__global__ void __launch_bounds__(256, 2) gemm_tf32(
    const float* __restrict__ A, const float* __restrict__ Bw,
    const float* __restrict__ bias, const float* __restrict__ res,
    float* __restrict__ C, int M, int N, int K)
{
    extern __shared__ float gsm[];
    float* As = gsm;                     // [3][128][32]
    float* Bs = gsm + 3 * GSTAGE;

    const int tid = threadIdx.x;
    const int lane = tid & 31, warp = tid >> 5;
    const int wm = (warp >> 1) * 32;
    const int wn = (warp & 1) * 64;
    const int r = lane >> 2, cq = lane & 3;
    const int m0 = blockIdx.y * 128, n0 = blockIdx.x * 128;

    // cp.async: thread writes rows lr+32c (c=0..3), 16B at swizzled col
    const int lr = tid >> 3;             // 0..31
    const int lc = (tid & 7) * 4;        // 0,4,..,28
    const int sw = (lr & 7) * 4;         // swizzle operand (same for all c)
    const float* Ag = A + (size_t)(m0 + lr) * K + lc;
    const float* Bg = Bw + (size_t)(n0 + lr) * K + lc;
    uint32_t sA[3][4], sB[3][4];
#pragma unroll
    for (int s = 0; s < 3; s++)
#pragma unroll
        for (int c = 0; c < 4; c++) {
            sA[s][c] = smem_u32(As + (size_t)s * GSTAGE + (lr + c * 32) * 32 + (lc ^ sw));
            sB[s][c] = smem_u32(Bs + (size_t)s * GSTAGE + (lr + c * 32) * 32 + (lc ^ sw));
        }

    float acc[2][8][4];
#pragma unroll
    for (int mt = 0; mt < 2; mt++)
#pragma unroll
        for (int nt = 0; nt < 8; nt++)
#pragma unroll
            for (int i = 0; i < 4; i++) acc[mt][nt][i] = 0.f;

    const int KT = K / 32;
    // prologue: fill stages 0,1
#pragma unroll
    for (int c = 0; c < 4; c++) {
        CPA(sA[0][c], Ag + (size_t)c * 32 * K);
        CPA(sB[0][c], Bg + (size_t)c * 32 * K);
    }
    CPC();
#pragma unroll
    for (int c = 0; c < 4; c++) {
        CPA(sA[1][c], Ag + (size_t)c * 32 * K + 32);
        CPA(sB[1][c], Bg + (size_t)c * 32 * K + 32);
    }
    CPC();

    const int fr4 = r * 4;               // fragment swizzle operand

    for (int kt = 0; kt < KT; kt++) {
        if (kt + 1 < KT) { CPW1(); } else { CPW0(); }
        __syncthreads();                 // stage kt ready; everyone done reading stage (kt+2)%3
        if (kt + 2 < KT) {
            const int st = (kt + 2) % 3;
            const int ko = (kt + 2) * 32;
#pragma unroll
            for (int c = 0; c < 4; c++) {
                CPA(sA[st][c], Ag + (size_t)c * 32 * K + ko);
                CPA(sB[st][c], Bg + (size_t)c * 32 * K + ko);
            }
            CPC();
        }
        const int buf = kt % 3;
        const float* Ab = As + (size_t)buf * GSTAGE;
        const float* Bb = Bs + (size_t)buf * GSTAGE;

#pragma unroll
        for (int ks = 0; ks < 4; ks++) {
            const int k0 = ks * 8;
            const int c0 = (k0 + cq) ^ fr4;
            const int c1 = (k0 + cq + 4) ^ fr4;
            uint32_t a[2][4], b[8][2];
#pragma unroll
            for (int mt = 0; mt < 2; mt++) {
                const float* ap = Ab + (wm + mt * 16 + r) * 32;
                a[mt][0] = __float_as_uint(ap[c0]);
                a[mt][1] = __float_as_uint(ap[8 * 32 + c0]);
                a[mt][2] = __float_as_uint(ap[c1]);
                a[mt][3] = __float_as_uint(ap[8 * 32 + c1]);
            }
#pragma unroll
            for (int nt = 0; nt < 8; nt++) {
                const float* bp = Bb + (wn + nt * 8 + r) * 32;
                b[nt][0] = __float_as_uint(bp[c0]);
                b[nt][1] = __float_as_uint(bp[c1]);
            }
#pragma unroll
            for (int mt = 0; mt < 2; mt++)
#pragma unroll
                for (int nt = 0; nt < 8; nt++)
                    MMA_TF32(acc[mt][nt], a[mt], b[nt]);
        }
    }

#pragma unroll
    for (int mt = 0; mt < 2; mt++) {
        const int row = m0 + wm + mt * 16 + r;
#pragma unroll
        for (int nt = 0; nt < 8; nt++) {
            const int col = n0 + wn + nt * 8 + cq * 2;
            const float2 bv = *(const float2*)(bias + col);
            float o0 = acc[mt][nt][0] + bv.x;
            float o1 = acc[mt][nt][1] + bv.y;
            float o2 = acc[mt][nt][2] + bv.x;
            float o3 = acc[mt][nt][3] + bv.y;
            if (OP == 1) {
                o0 = tf32r(0.5f * o0 * (1.0f + erff(o0 * 0.7071067811865475f)));
                o1 = tf32r(0.5f * o1 * (1.0f + erff(o1 * 0.7071067811865475f)));
                o2 = tf32r(0.5f * o2 * (1.0f + erff(o2 * 0.7071067811865475f)));
                o3 = tf32r(0.5f * o3 * (1.0f + erff(o3 * 0.7071067811865475f)));
            }
            if (OP == 2) {
                const float2 r0 = *(const float2*)(res + (size_t)row * N + col);
                const float2 r1 = *(const float2*)(res + (size_t)(row + 8) * N + col);
                o0 += r0.x; o1 += r0.y; o2 += r1.x; o3 += r1.y;
            }
            *(float2*)(C + (size_t)row * N + col) = make_float2(o0, o1);
            *(float2*)(C + (size_t)(row + 8) * N + col) = make_float2(o2, o3);
        }
    }
}

// ---------------- LayerNorm: one warp per row ----------------
__global__ void ln_warp_kernel(const float* __restrict__ x, const float* __restrict__ g,
                               const float* __restrict__ bt, float* __restrict__ y,
                               long in_row_stride, int nrows)
{
    const int row = blockIdx.x * 8 + (threadIdx.x >> 5);
    if (row >= nrows) return;
    const int lane = threadIdx.x & 31;
    const float4* xr = (const float4*)(x + (size_t)row * in_row_stride);
    float4 v[3];
    v[0] = xr[lane]; v[1] = xr[lane + 32]; v[2] = xr[lane + 64];
    float s = 0.f, q = 0.f;
#pragma unroll
    for (int t = 0; t < 3; t++) {
        s += v[t].x + v[t].y + v[t].z + v[t].w;
        q += v[t].x * v[t].x + v[t].y * v[t].y + v[t].z * v[t].z + v[t].w * v[t].w;
    }
#pragma unroll
    for (int o = 16; o; o >>= 1) {
        s += __shfl_xor_sync(0xffffffffu, s, o);
        q += __shfl_xor_sync(0xffffffffu, q, o);
    }
    const float mean = s * (1.0f / DD);
    const float rstd = rsqrtf(q * (1.0f / DD) - mean * mean + 1e-5f);
    const float4* gp = (const float4*)g;
    const float4* bp = (const float4*)bt;
    float4* yr = (float4*)(y + (size_t)row * DD);
#pragma unroll
    for (int t = 0; t < 3; t++) {
        float4 gv = gp[lane + 32 * t], bv = bp[lane + 32 * t];
        float4 o;
        o.x = tf32r((v[t].x - mean) * rstd * gv.x + bv.x);
        o.y = tf32r((v[t].y - mean) * rstd * gv.y + bv.y);
        o.z = tf32r((v[t].z - mean) * rstd * gv.z + bv.z);
        o.w = tf32r((v[t].w - mean) * rstd * gv.w + bv.w);
        yr[lane + 32 * t] = o;
    }
}

// ---------------- fused flash attention, fp32 smem + split-at-use 3xTF32 ----------------
#define FA_SMEM ((128 + 64 + 64 + 128) * 68 * 4)

__global__ void __launch_bounds__(256, 2) flash_attn(const float* __restrict__ qkv,
                                                     float* __restrict__ ctx)
{
    extern __shared__ float sm[];
    float (*Qs)[68] = (float(*)[68])sm;
    float (*Ks)[68] = Qs + 128;
    float (*Vt)[68] = Ks + 64;
    float (*Ps)[68] = Vt + 64;

    const int bh = blockIdx.y;
    const int b = bh / HEADS, h = bh - b * HEADS;
    const int i0 = blockIdx.x * 128;
    const float* base = qkv + (size_t)b * SS * (3 * DD) + h * HD;

    const int tid = threadIdx.x;
    const int lane = tid & 31, warp = tid >> 5;
    const int wm = warp * 16;
    const int r = lane >> 2, cq = lane & 3;
    const bool wactive = (i0 + wm) < SS;

    for (int idx = tid; idx < 128 * 16; idx += 256) {
        int ii = idx >> 4, d4 = (idx & 15) * 4;
        int i = i0 + ii;
        float4 v = make_float4(0.f, 0.f, 0.f, 0.f);
        if (i < SS) v = *(const float4*)(base + (size_t)i * (3 * DD) + d4);
        Qs[ii][d4 + 0] = v.x * 0.125f;
        Qs[ii][d4 + 1] = v.y * 0.125f;
        Qs[ii][d4 + 2] = v.z * 0.125f;
        Qs[ii][d4 + 3] = v.w * 0.125f;
    }

    float o[8][4];
#pragma unroll
    for (int nt = 0; nt < 8; nt++)
#pragma unroll
        for (int i = 0; i < 4; i++) o[nt][i] = 0.f;
    float m0 = -1e30f, m1 = -1e30f, l0 = 0.f, l1 = 0.f;

    for (int jc = 0; jc < 4; jc++) {
        const int jb = jc * 64;
        const int ntmax = (jc < 3) ? 8 : 1;
        __syncthreads();

        for (int idx = tid; idx < 64 * 16; idx += 256) {
            int jj = idx >> 4, d4 = (idx & 15) * 4;
            int j = jb + jj;
            float4 v = make_float4(0.f, 0.f, 0.f, 0.f);
            if (j < SS) v = *(const float4*)(base + (size_t)j * (3 * DD) + DD + d4);
            Ks[jj][d4 + 0] = v.x; Ks[jj][d4 + 1] = v.y;
            Ks[jj][d4 + 2] = v.z; Ks[jj][d4 + 3] = v.w;
        }
        for (int idx = tid; idx < 64 * 16; idx += 256) {
            int jj = idx >> 4, d4 = (idx & 15) * 4;
            int j = jb + jj;
            float4 v = make_float4(0.f, 0.f, 0.f, 0.f);
            if (j < SS) v = *(const float4*)(base + (size_t)j * (3 * DD) + 2 * DD + d4);
            Vt[d4 + 0][jj] = v.x; Vt[d4 + 1][jj] = v.y;
            Vt[d4 + 2][jj] = v.z; Vt[d4 + 3][jj] = v.w;
        }
        __syncthreads();

        if (wactive) {
            float s[8][4];
#pragma unroll
            for (int nt = 0; nt < 8; nt++)
#pragma unroll
                for (int i = 0; i < 4; i++) s[nt][i] = 0.f;

#pragma unroll
            for (int k0 = 0; k0 < 64; k0 += 8) {
                uint32_t ahi[4], alo[4];
                split_u(Qs[wm + r][k0 + cq],         ahi[0], alo[0]);
                split_u(Qs[wm + r + 8][k0 + cq],     ahi[1], alo[1]);
                split_u(Qs[wm + r][k0 + cq + 4],     ahi[2], alo[2]);
                split_u(Qs[wm + r + 8][k0 + cq + 4], ahi[3], alo[3]);
                for (int nt = 0; nt < ntmax; nt++) {
                    uint32_t bhi[2], blo[2];
                    split_u(Ks[nt * 8 + r][k0 + cq],     bhi[0], blo[0]);
                    split_u(Ks[nt * 8 + r][k0 + cq + 4], bhi[1], blo[1]);
                    MMA_TF32(s[nt], ahi, bhi);
                    MMA_TF32(s[nt], ahi, blo);
                    MMA_TF32(s[nt], alo, bhi);
                }
            }

            float mx0 = -1e30f, mx1 = -1e30f;
            for (int nt = 0; nt < ntmax; nt++) {
                int col = jb + nt * 8 + cq * 2;
                if (col >= SS)     { s[nt][0] = s[nt][2] = -1e30f; }
                if (col + 1 >= SS) { s[nt][1] = s[nt][3] = -1e30f; }
                mx0 = fmaxf(mx0, fmaxf(s[nt][0], s[nt][1]));
                mx1 = fmaxf(mx1, fmaxf(s[nt][2], s[nt][3]));
            }
            mx0 = fmaxf(mx0, __shfl_xor_sync(0xffffffffu, mx0, 1));
            mx0 = fmaxf(mx0, __shfl_xor_sync(0xffffffffu, mx0, 2));
            mx1 = fmaxf(mx1, __shfl_xor_sync(0xffffffffu, mx1, 1));
            mx1 = fmaxf(mx1, __shfl_xor_sync(0xffffffffu, mx1, 2));

            const float mn0 = fmaxf(m0, mx0), mn1 = fmaxf(m1, mx1);
            const float sc0 = expf(m0 - mn0), sc1 = expf(m1 - mn1);
            float sum0 = 0.f, sum1 = 0.f;
            for (int nt = 0; nt < ntmax; nt++) {
                int cc = nt * 8 + cq * 2;
                float p0 = expf(s[nt][0] - mn0);
                float p1 = expf(s[nt][1] - mn0);
                float p2 = expf(s[nt][2] - mn1);
                float p3 = expf(s[nt][3] - mn1);
                sum0 += p0 + p1;
                sum1 += p2 + p3;
                Ps[wm + r][cc] = p0;     Ps[wm + r][cc + 1] = p1;
                Ps[wm + r + 8][cc] = p2; Ps[wm + r + 8][cc + 1] = p3;
            }
            sum0 += __shfl_xor_sync(0xffffffffu, sum0, 1);
            sum0 += __shfl_xor_sync(0xffffffffu, sum0, 2);
            sum1 += __shfl_xor_sync(0xffffffffu, sum1, 1);
            sum1 += __shfl_xor_sync(0xffffffffu, sum1, 2);
            l0 = l0 * sc0 + sum0;
            l1 = l1 * sc1 + sum1;
            m0 = mn0; m1 = mn1;
#pragma unroll
            for (int nt = 0; nt < 8; nt++) {
                o[nt][0] *= sc0; o[nt][1] *= sc0;
                o[nt][2] *= sc1; o[nt][3] *= sc1;
            }
            __syncwarp();

            for (int k0 = 0; k0 < ntmax * 8; k0 += 8) {
                uint32_t ahi[4], alo[4];
                split_u(Ps[wm + r][k0 + cq],         ahi[0], alo[0]);
                split_u(Ps[wm + r + 8][k0 + cq],     ahi[1], alo[1]);
                split_u(Ps[wm + r][k0 + cq + 4],     ahi[2], alo[2]);
                split_u(Ps[wm + r + 8][k0 + cq + 4], ahi[3], alo[3]);
#pragma unroll
                for (int nt = 0; nt < 8; nt++) {
                    uint32_t bhi[2], blo[2];
                    split_u(Vt[nt * 8 + r][k0 + cq],     bhi[0], blo[0]);
                    split_u(Vt[nt * 8 + r][k0 + cq + 4], bhi[1], blo[1]);
                    MMA_TF32(o[nt], ahi, bhi);
                    MMA_TF32(o[nt], ahi, blo);
                    MMA_TF32(o[nt], alo, bhi);
                }
            }
        }
    }

    if (wactive) {
        const float inv0 = 1.0f / l0, inv1 = 1.0f / l1;
        const int row0 = i0 + wm + r, row1 = row0 + 8;
#pragma unroll
        for (int nt = 0; nt < 8; nt++) {
            const int col = h * HD + nt * 8 + cq * 2;
            if (row0 < SS) {
                float2 ov = make_float2(tf32r(o[nt][0] * inv0), tf32r(o[nt][1] * inv0));
                *(float2*)&ctx[((size_t)b * SS + row0) * DD + col] = ov;
            }
            if (row1 < SS) {
                float2 ov = make_float2(tf32r(o[nt][2] * inv1), tf32r(o[nt][3] * inv1));
                *(float2*)&ctx[((size_t)b * SS + row1) * DD + col] = ov;
            }
        }
    }
}

// ---------------- classifier head ----------------
__global__ void head_kernel(const float* __restrict__ cls, const float* __restrict__ hw,
                            float* __restrict__ out)
{
    __shared__ float s[DD];
    int b = blockIdx.x;
    for (int k = threadIdx.x; k < DD; k += blockDim.x) s[k] = cls[(size_t)b * DD + k];
    __syncthreads();
    int c = threadIdx.x;
    if (c < NCLS) {
        const float* w = hw + (size_t)c * DD;
        float acc = 0.f;
#pragma unroll 8
        for (int k = 0; k < DD; k++) acc += s[k] * w[k];
        out[(size_t)b * NCLS + c] = acc;
    }
}

// ---------------- launch ----------------
extern "C" void kernel_launch(void* const* d_in, const int* in_sizes, int n_in,
                              void* d_out, int out_size) {
    const float* x         = (const float*)d_in[0];
    const float* patch_w   = (const float*)d_in[1];
    const float* patch_b   = (const float*)d_in[2];
    const float* cls_token = (const float*)d_in[3];
    const float* pos_embed = (const float*)d_in[4];
    const float* ln1_g     = (const float*)d_in[5];
    const float* ln1_b     = (const float*)d_in[6];
    const float* qkv_w     = (const float*)d_in[7];
    const float* qkv_b     = (const float*)d_in[8];
    const float* out_w     = (const float*)d_in[9];
    const float* out_b     = (const float*)d_in[10];
    const float* ln2_g     = (const float*)d_in[11];
    const float* ln2_b     = (const float*)d_in[12];
    const float* fc1_w     = (const float*)d_in[13];
    const float* fc1_b     = (const float*)d_in[14];
    const float* fc2_w     = (const float*)d_in[15];
    const float* fc2_b     = (const float*)d_in[16];
    const float* lnf_g     = (const float*)d_in[17];
    const float* lnf_b     = (const float*)d_in[18];
    const float* head_w    = (const float*)d_in[19];
    float* out = (float*)d_out;

    float *patches, *tok, *h, *xn, *qkv, *ctx, *hid, *cls, *w;
    cudaGetSymbolAddress((void**)&patches, g_patches);
    cudaGetSymbolAddress((void**)&tok, g_tok);
    cudaGetSymbolAddress((void**)&h, g_h);
    cudaGetSymbolAddress((void**)&xn, g_xn);
    cudaGetSymbolAddress((void**)&qkv, g_qkv);
    cudaGetSymbolAddress((void**)&ctx, g_ctx);
    cudaGetSymbolAddress((void**)&hid, g_hid);
    cudaGetSymbolAddress((void**)&cls, g_cls);
    cudaGetSymbolAddress((void**)&w, g_w);

    cudaFuncSetAttribute(gemm_tf32<0>, cudaFuncAttributeMaxDynamicSharedMemorySize, GEMM_SMEM);
    cudaFuncSetAttribute(gemm_tf32<1>, cudaFuncAttributeMaxDynamicSharedMemorySize, GEMM_SMEM);
    cudaFuncSetAttribute(gemm_tf32<2>, cudaFuncAttributeMaxDynamicSharedMemorySize, GEMM_SMEM);
    cudaFuncSetAttribute(flash_attn, cudaFuncAttributeMaxDynamicSharedMemorySize, FA_SMEM);

    // 0,1: weight rounding; 2: patchify; 3: patch GEMM (profiled index)
    round_w_a<<<(W_FC1 / 4 + 255) / 256, 256>>>(patch_w, qkv_w, out_w, w);
    round_w_b<<<((W_TOTAL - W_FC1) / 4 + 255) / 256, 256>>>(fc1_w, fc2_w, w);
    patchify_kernel<<<(PTOK * PATCH_DIM + 255) / 256, 256>>>(x, patches);
    gemm_tf32<0><<<dim3(DD / 128, PTOK / 128), 256, GEMM_SMEM>>>(
        patches, w + W_PATCH, patch_b, nullptr, tok, PTOK, DD, PATCH_DIM);
    assemble_kernel<<<(TOK * DD + 255) / 256, 256>>>(tok, cls_token, pos_embed, h);

    for (int i = 0; i < DEPTH; i++) {
        ln_warp_kernel<<<(TOK + 7) / 8, 256>>>(h, ln1_g + i * DD, ln1_b + i * DD, xn, DD, TOK);
        gemm_tf32<0><<<dim3(3 * DD / 128, TOK / 128), 256, GEMM_SMEM>>>(
            xn, w + W_QKV + (size_t)i * 3 * DD * DD, qkv_b + (size_t)i * 3 * DD,
            nullptr, qkv, TOK, 3 * DD, DD);
        flash_attn<<<dim3(2, BH), 256, FA_SMEM>>>(qkv, ctx);
        gemm_tf32<2><<<dim3(DD / 128, TOK / 128), 256, GEMM_SMEM>>>(
            ctx, w + W_OUT + (size_t)i * DD * DD, out_b + (size_t)i * DD, h, h, TOK, DD, DD);
        ln_warp_kernel<<<(TOK + 7) / 8, 256>>>(h, ln2_g + i * DD, ln2_b + i * DD, xn, DD, TOK);
        gemm_tf32<1><<<dim3(HID / 128, TOK / 128), 256, GEMM_SMEM>>>(
            xn, w + W_FC1 + (size_t)i * HID * DD, fc1_b + (size_t)i * HID,
            nullptr, hid, TOK, HID, DD);
        gemm_tf32<2><<<dim3(DD / 128, TOK / 128), 256, GEMM_SMEM>>>(
            hid, w + W_FC2 + (size_t)i * DD * HID, fc2_b + (size_t)i * DD, h, h, TOK, DD, HID);
    }

    ln_warp_kernel<<<(BB + 7) / 8, 256>>>(h, lnf_g, lnf_b, cls, (long)SS * DD, BB);
    head_kernel<<<BB, 128>>>(cls, head_w, out);
}

// round 9
// speedup vs baseline: 1.5252x; 1.0567x over previous
#include <cuda_runtime.h>
#include <math.h>
#include <stdint.h>

// ---------------- problem constants ----------------
#define BB 128
#define CC 3
#define IMG 224
#define PP 16
#define HP 14
#define NP 196
#define SS 197
#define DD 384
#define HEADS 6
#define HD 64
#define DEPTH 12
#define HID 1536
#define NCLS 100
#define PATCH_DIM 768
#define TOK (BB*SS)    // 25216
#define PTOK (BB*NP)   // 25088
#define BH (BB*HEADS)  // 768

// ---------------- scratch ----------------
__device__ float g_patches[PTOK * PATCH_DIM];
__device__ float g_tok[PTOK * DD];
__device__ float g_h[TOK * DD];
__device__ float g_xn[TOK * DD];
__device__ float g_qkv[TOK * 3 * DD];
__device__ float g_ctx[TOK * DD];
__device__ float g_hid[TOK * HID];
__device__ float g_cls[BB * DD];
// tf32-rounded weights (offsets in floats)
#define W_PATCH 0
#define W_QKV   294912
#define W_OUT   5603328
#define W_FC1   7372800
#define W_FC2   14450688
#define W_TOTAL 21528576
__device__ float g_w[W_TOTAL];

// ---------------- helpers ----------------
__device__ __forceinline__ float tf32r(float x) {
    uint32_t u;
    asm("cvt.rna.tf32.f32 %0, %1;" : "=r"(u) : "f"(x));
    return __uint_as_float(u);
}
__device__ __forceinline__ void split_u(float x, uint32_t& hi, uint32_t& lo) {
    float h = tf32r(x);
    hi = __float_as_uint(h);
    lo = __float_as_uint(tf32r(x - h));
}
__device__ __forceinline__ uint32_t smem_u32(const void* p) {
    return (uint32_t)__cvta_generic_to_shared(p);
}
#define CPA(dst, src) asm volatile("cp.async.cg.shared.global [%0], [%1], 16;" :: "r"(dst), "l"(src))
#define CPC() asm volatile("cp.async.commit_group;")
#define CPW0() asm volatile("cp.async.wait_group 0;")
#define CPW1() asm volatile("cp.async.wait_group 1;")
#define MMA_TF32(d, a, b) asm volatile( \
    "mma.sync.aligned.m16n8k8.row.col.f32.tf32.tf32.f32 " \
    "{%0,%1,%2,%3},{%4,%5,%6,%7},{%8,%9},{%0,%1,%2,%3};" \
    : "+f"(d[0]), "+f"(d[1]), "+f"(d[2]), "+f"(d[3]) \
    : "r"(a[0]), "r"(a[1]), "r"(a[2]), "r"(a[3]), "r"(b[0]), "r"(b[1]))
#define MMA_TF32_2(d, a, b0v, b1v) asm volatile( \
    "mma.sync.aligned.m16n8k8.row.col.f32.tf32.tf32.f32 " \
    "{%0,%1,%2,%3},{%4,%5,%6,%7},{%8,%9},{%0,%1,%2,%3};" \
    : "+f"(d[0]), "+f"(d[1]), "+f"(d[2]), "+f"(d[3]) \
    : "r"(a[0]), "r"(a[1]), "r"(a[2]), "r"(a[3]), "r"(b0v), "r"(b1v))
#define LDSM_X4(f, addr) asm volatile( \
    "ldmatrix.sync.aligned.m8n8.x4.shared.b16 {%0,%1,%2,%3}, [%4];" \
    : "=r"((f)[0]), "=r"((f)[1]), "=r"((f)[2]), "=r"((f)[3]) : "r"(addr))

// ---------------- weight rounding, split into 2 launches (profiler indexing) ----------------
__global__ void round_w_a(const float* __restrict__ pw, const float* __restrict__ qw,
                          const float* __restrict__ ow, float* __restrict__ w) {
    int i = blockIdx.x * blockDim.x + threadIdx.x;
    if (i >= W_FC1 / 4) return;
    int f = i * 4;
    const float* src; int off;
    if (f < W_QKV)      { src = pw; off = f - W_PATCH; }
    else if (f < W_OUT) { src = qw; off = f - W_QKV; }
    else                { src = ow; off = f - W_OUT; }
    float4 v = *(const float4*)(src + off);
    v.x = tf32r(v.x); v.y = tf32r(v.y); v.z = tf32r(v.z); v.w = tf32r(v.w);
    ((float4*)w)[i] = v;
}
__global__ void round_w_b(const float* __restrict__ f1, const float* __restrict__ f2,
                          float* __restrict__ w) {
    int i = blockIdx.x * blockDim.x + threadIdx.x;
    if (i >= (W_TOTAL - W_FC1) / 4) return;
    int f = W_FC1 + i * 4;
    const float* src; int off;
    if (f < W_FC2) { src = f1; off = f - W_FC1; }
    else           { src = f2; off = f - W_FC2; }
    float4 v = *(const float4*)(src + off);
    v.x = tf32r(v.x); v.y = tf32r(v.y); v.z = tf32r(v.z); v.w = tf32r(v.w);
    ((float4*)(w + W_FC1))[i] = v;
}

// ---------------- patchify (+tf32 round) ----------------
__global__ void patchify_kernel(const float* __restrict__ x, float* __restrict__ patches) {
    int idx = blockIdx.x * blockDim.x + threadIdx.x;
    if (idx >= PTOK * PATCH_DIM) return;
    int t = idx / PATCH_DIM;
    int k = idx - t * PATCH_DIM;
    int b = t / NP;
    int n = t - b * NP;
    int ph = n / HP, pw = n - ph * HP;
    int c = k >> 8;
    int py = (k >> 4) & 15;
    int px = k & 15;
    patches[idx] = tf32r(x[(((size_t)b * CC + c) * IMG + (ph * PP + py)) * IMG + (pw * PP + px)]);
}

// ---------------- assemble h = [cls; tok] + pos ----------------
__global__ void assemble_kernel(const float* __restrict__ tok, const float* __restrict__ cls_token,
                                const float* __restrict__ pos, float* __restrict__ h) {
    int idx = blockIdx.x * blockDim.x + threadIdx.x;
    if (idx >= TOK * DD) return;
    int row = idx / DD;
    int d = idx - row * DD;
    int b = row / SS;
    int s = row - b * SS;
    float v = (s == 0) ? cls_token[d] : tok[((size_t)b * NP + (s - 1)) * DD + d];
    h[idx] = v + pos[s * DD + d];
}

// ---------------- tf32 NT GEMM: swizzled smem, 3-stage cp.async, ldmatrix fragments ----------------
// smem stage: 128 rows x 32 floats (A and B). element (row,k) at col k ^ (4*(row&7)).
#define GSTAGE 4096                         // floats per stage per operand
#define GEMM_SMEM (3 * 2 * GSTAGE * 4)      // 98304 B

template <int OP>
__global__ void __launch_bounds__(256, 2) gemm_tf32(
    const float* __restrict__ A, const float* __restrict__ Bw,
    const float* __restrict__ bias, const float* __restrict__ res,
    float* __restrict__ C, int M, int N, int K)
{
    extern __shared__ float gsm[];
    float* As = gsm;                     // [3][128][32]
    float* Bs = gsm + 3 * GSTAGE;

    const int tid = threadIdx.x;
    const int lane = tid & 31, warp = tid >> 5;
    const int wm = (warp >> 1) * 32;
    const int wn = (warp & 1) * 64;
    const int r = lane >> 2, cq = lane & 3;
    const int m0 = blockIdx.y * 128, n0 = blockIdx.x * 128;

    // cp.async store mapping
    const int lr = tid >> 3;             // 0..31
    const int lc = (tid & 7) * 4;        // 0,4,..,28
    const int sw = (lr & 7) * 4;
    const float* Ag = A + (size_t)(m0 + lr) * K + lc;
    const float* Bg = Bw + (size_t)(n0 + lr) * K + lc;
    uint32_t sA[3][4], sB[3][4];
#pragma unroll
    for (int s = 0; s < 3; s++)
#pragma unroll
        for (int c = 0; c < 4; c++) {
            sA[s][c] = smem_u32(As + (size_t)s * GSTAGE + (lr + c * 32) * 32 + (lc ^ sw));
            sB[s][c] = smem_u32(Bs + (size_t)s * GSTAGE + (lr + c * 32) * 32 + (lc ^ sw));
        }

    // ldmatrix per-lane addressing
    // A x4 group (per mt): matrices [rows0-7/blk b, rows8-15/blk b, rows0-7/b+1, rows8-15/b+1]
    const int lm = lane >> 3;            // matrix index 0..3
    const int rit = lane & 7;            // row within tile
    const int arow0 = wm + ((lm & 1) * 8) + rit;         // mt=0 abs row
    const int abo = lm >> 1;                             // block offset 0/1
    const uint32_t aswz0 = (uint32_t)(arow0 & 7);
    const uint32_t aswz1 = (uint32_t)((arow0 + 16) & 7); // == aswz0 (16 ≡ 0 mod 8)
    // B x4 group g: matrices [nt=2g/b, nt=2g/b+1, nt=2g+1/b, nt=2g+1/b+1]
    const int bnt = lm >> 1;                             // 0/0/1/1 within pair
    const int bbo = lm & 1;
    uint32_t browoff[4], bswz[4];
#pragma unroll
    for (int g = 0; g < 4; g++) {
        int brow = wn + (2 * g + bnt) * 8 + rit;
        browoff[g] = (uint32_t)(brow * 128);
        bswz[g] = (uint32_t)(brow & 7);
    }
    const uint32_t smemA0 = smem_u32(As);
    const uint32_t smemB0 = smem_u32(Bs);

    float acc[2][8][4];
#pragma unroll
    for (int mt = 0; mt < 2; mt++)
#pragma unroll
        for (int nt = 0; nt < 8; nt++)
#pragma unroll
            for (int i = 0; i < 4; i++) acc[mt][nt][i] = 0.f;

    const int KT = K / 32;
    // prologue: fill stages 0,1
#pragma unroll
    for (int c = 0; c < 4; c++) {
        CPA(sA[0][c], Ag + (size_t)c * 32 * K);
        CPA(sB[0][c], Bg + (size_t)c * 32 * K);
    }
    CPC();
#pragma unroll
    for (int c = 0; c < 4; c++) {
        CPA(sA[1][c], Ag + (size_t)c * 32 * K + 32);
        CPA(sB[1][c], Bg + (size_t)c * 32 * K + 32);
    }
    CPC();

    for (int kt = 0; kt < KT; kt++) {
        if (kt + 1 < KT) { CPW1(); } else { CPW0(); }
        __syncthreads();
        if (kt + 2 < KT) {
            const int st = (kt + 2) % 3;
            const int ko = (kt + 2) * 32;
#pragma unroll
            for (int c = 0; c < 4; c++) {
                CPA(sA[st][c], Ag + (size_t)c * 32 * K + ko);
                CPA(sB[st][c], Bg + (size_t)c * 32 * K + ko);
            }
            CPC();
        }
        const int buf = kt % 3;
        const uint32_t abase = smemA0 + (uint32_t)buf * (GSTAGE * 4);
        const uint32_t bbase = smemB0 + (uint32_t)buf * (GSTAGE * 4);

#pragma unroll
        for (int ks = 0; ks < 4; ks++) {
            const uint32_t kb = (uint32_t)(ks * 2);
            uint32_t a[2][4], bf[4][4];
            // A fragments: 2 x ldmatrix.x4
            LDSM_X4(a[0], abase + (uint32_t)(arow0 * 128) + (((kb + abo) ^ aswz0) << 4));
            LDSM_X4(a[1], abase + (uint32_t)((arow0 + 16) * 128) + (((kb + abo) ^ aswz1) << 4));
            // B fragments: 4 x ldmatrix.x4 (nt pairs)
#pragma unroll
            for (int g = 0; g < 4; g++)
                LDSM_X4(bf[g], bbase + browoff[g] + (((kb + bbo) ^ bswz[g]) << 4));
#pragma unroll
            for (int mt = 0; mt < 2; mt++)
#pragma unroll
                for (int nt = 0; nt < 8; nt++)
                    MMA_TF32_2(acc[mt][nt], a[mt],
                               bf[nt >> 1][(nt & 1) * 2], bf[nt >> 1][(nt & 1) * 2 + 1]);
        }
    }

#pragma unroll
    for (int mt = 0; mt < 2; mt++) {
        const int row = m0 + wm + mt * 16 + r;
#pragma unroll
        for (int nt = 0; nt < 8; nt++) {
            const int col = n0 + wn + nt * 8 + cq * 2;
            const float2 bv = *(const float2*)(bias + col);
            float o0 = acc[mt][nt][0] + bv.x;
            float o1 = acc[mt][nt][1] + bv.y;
            float o2 = acc[mt][nt][2] + bv.x;
            float o3 = acc[mt][nt][3] + bv.y;
            if (OP == 1) {
                o0 = tf32r(0.5f * o0 * (1.0f + erff(o0 * 0.7071067811865475f)));
                o1 = tf32r(0.5f * o1 * (1.0f + erff(o1 * 0.7071067811865475f)));
                o2 = tf32r(0.5f * o2 * (1.0f + erff(o2 * 0.7071067811865475f)));
                o3 = tf32r(0.5f * o3 * (1.0f + erff(o3 * 0.7071067811865475f)));
            }
            if (OP == 2) {
                const float2 r0 = *(const float2*)(res + (size_t)row * N + col);
                const float2 r1 = *(const float2*)(res + (size_t)(row + 8) * N + col);
                o0 += r0.x; o1 += r0.y; o2 += r1.x; o3 += r1.y;
            }
            *(float2*)(C + (size_t)row * N + col) = make_float2(o0, o1);
            *(float2*)(C + (size_t)(row + 8) * N + col) = make_float2(o2, o3);
        }
    }
}

// ---------------- LayerNorm: one warp per row ----------------
__global__ void ln_warp_kernel(const float* __restrict__ x, const float* __restrict__ g,
                               const float* __restrict__ bt, float* __restrict__ y,
                               long in_row_stride, int nrows)
{
    const int row = blockIdx.x * 8 + (threadIdx.x >> 5);
    if (row >= nrows) return;
    const int lane = threadIdx.x & 31;
    const float4* xr = (const float4*)(x + (size_t)row * in_row_stride);
    float4 v[3];
    v[0] = xr[lane]; v[1] = xr[lane + 32]; v[2] = xr[lane + 64];
    float s = 0.f, q = 0.f;
#pragma unroll
    for (int t = 0; t < 3; t++) {
        s += v[t].x + v[t].y + v[t].z + v[t].w;
        q += v[t].x * v[t].x + v[t].y * v[t].y + v[t].z * v[t].z + v[t].w * v[t].w;
    }
#pragma unroll
    for (int o = 16; o; o >>= 1) {
        s += __shfl_xor_sync(0xffffffffu, s, o);
        q += __shfl_xor_sync(0xffffffffu, q, o);
    }
    const float mean = s * (1.0f / DD);
    const float rstd = rsqrtf(q * (1.0f / DD) - mean * mean + 1e-5f);
    const float4* gp = (const float4*)g;
    const float4* bp = (const float4*)bt;
    float4* yr = (float4*)(y + (size_t)row * DD);
#pragma unroll
    for (int t = 0; t < 3; t++) {
        float4 gv = gp[lane + 32 * t], bv = bp[lane + 32 * t];
        float4 o;
        o.x = tf32r((v[t].x - mean) * rstd * gv.x + bv.x);
        o.y = tf32r((v[t].y - mean) * rstd * gv.y + bv.y);
        o.z = tf32r((v[t].z - mean) * rstd * gv.z + bv.z);
        o.w = tf32r((v[t].w - mean) * rstd * gv.w + bv.w);
        yr[lane + 32 * t] = o;
    }
}

// ---------------- fused flash attention, fp32 smem + split-at-use 3xTF32 ----------------
#define FA_SMEM ((128 + 64 + 64 + 128) * 68 * 4)

__global__ void __launch_bounds__(256, 2) flash_attn(const float* __restrict__ qkv,
                                                     float* __restrict__ ctx)
{
    extern __shared__ float sm[];
    float (*Qs)[68] = (float(*)[68])sm;
    float (*Ks)[68] = Qs + 128;
    float (*Vt)[68] = Ks + 64;
    float (*Ps)[68] = Vt + 64;

    const int bh = blockIdx.y;
    const int b = bh / HEADS, h = bh - b * HEADS;
    const int i0 = blockIdx.x * 128;
    const float* base = qkv + (size_t)b * SS * (3 * DD) + h * HD;

    const int tid = threadIdx.x;
    const int lane = tid & 31, warp = tid >> 5;
    const int wm = warp * 16;
    const int r = lane >> 2, cq = lane & 3;
    const bool wactive = (i0 + wm) < SS;

    for (int idx = tid; idx < 128 * 16; idx += 256) {
        int ii = idx >> 4, d4 = (idx & 15) * 4;
        int i = i0 + ii;
        float4 v = make_float4(0.f, 0.f, 0.f, 0.f);
        if (i < SS) v = *(const float4*)(base + (size_t)i * (3 * DD) + d4);
        Qs[ii][d4 + 0] = v.x * 0.125f;
        Qs[ii][d4 + 1] = v.y * 0.125f;
        Qs[ii][d4 + 2] = v.z * 0.125f;
        Qs[ii][d4 + 3] = v.w * 0.125f;
    }

    float o[8][4];
#pragma unroll
    for (int nt = 0; nt < 8; nt++)
#pragma unroll
        for (int i = 0; i < 4; i++) o[nt][i] = 0.f;
    float m0 = -1e30f, m1 = -1e30f, l0 = 0.f, l1 = 0.f;

    for (int jc = 0; jc < 4; jc++) {
        const int jb = jc * 64;
        const int ntmax = (jc < 3) ? 8 : 1;
        __syncthreads();

        for (int idx = tid; idx < 64 * 16; idx += 256) {
            int jj = idx >> 4, d4 = (idx & 15) * 4;
            int j = jb + jj;
            float4 v = make_float4(0.f, 0.f, 0.f, 0.f);
            if (j < SS) v = *(const float4*)(base + (size_t)j * (3 * DD) + DD + d4);
            Ks[jj][d4 + 0] = v.x; Ks[jj][d4 + 1] = v.y;
            Ks[jj][d4 + 2] = v.z; Ks[jj][d4 + 3] = v.w;
        }
        for (int idx = tid; idx < 64 * 16; idx += 256) {
            int jj = idx >> 4, d4 = (idx & 15) * 4;
            int j = jb + jj;
            float4 v = make_float4(0.f, 0.f, 0.f, 0.f);
            if (j < SS) v = *(const float4*)(base + (size_t)j * (3 * DD) + 2 * DD + d4);
            Vt[d4 + 0][jj] = v.x; Vt[d4 + 1][jj] = v.y;
            Vt[d4 + 2][jj] = v.z; Vt[d4 + 3][jj] = v.w;
        }
        __syncthreads();

        if (wactive) {
            float s[8][4];
#pragma unroll
            for (int nt = 0; nt < 8; nt++)
#pragma unroll
                for (int i = 0; i < 4; i++) s[nt][i] = 0.f;

#pragma unroll
            for (int k0 = 0; k0 < 64; k0 += 8) {
                uint32_t ahi[4], alo[4];
                split_u(Qs[wm + r][k0 + cq],         ahi[0], alo[0]);
                split_u(Qs[wm + r + 8][k0 + cq],     ahi[1], alo[1]);
                split_u(Qs[wm + r][k0 + cq + 4],     ahi[2], alo[2]);
                split_u(Qs[wm + r + 8][k0 + cq + 4], ahi[3], alo[3]);
                for (int nt = 0; nt < ntmax; nt++) {
                    uint32_t bhi[2], blo[2];
                    split_u(Ks[nt * 8 + r][k0 + cq],     bhi[0], blo[0]);
                    split_u(Ks[nt * 8 + r][k0 + cq + 4], bhi[1], blo[1]);
                    MMA_TF32(s[nt], ahi, bhi);
                    MMA_TF32(s[nt], ahi, blo);
                    MMA_TF32(s[nt], alo, bhi);
                }
            }

            float mx0 = -1e30f, mx1 = -1e30f;
            for (int nt = 0; nt < ntmax; nt++) {
                int col = jb + nt * 8 + cq * 2;
                if (col >= SS)     { s[nt][0] = s[nt][2] = -1e30f; }
                if (col + 1 >= SS) { s[nt][1] = s[nt][3] = -1e30f; }
                mx0 = fmaxf(mx0, fmaxf(s[nt][0], s[nt][1]));
                mx1 = fmaxf(mx1, fmaxf(s[nt][2], s[nt][3]));
            }
            mx0 = fmaxf(mx0, __shfl_xor_sync(0xffffffffu, mx0, 1));
            mx0 = fmaxf(mx0, __shfl_xor_sync(0xffffffffu, mx0, 2));
            mx1 = fmaxf(mx1, __shfl_xor_sync(0xffffffffu, mx1, 1));
            mx1 = fmaxf(mx1, __shfl_xor_sync(0xffffffffu, mx1, 2));

            const float mn0 = fmaxf(m0, mx0), mn1 = fmaxf(m1, mx1);
            const float sc0 = expf(m0 - mn0), sc1 = expf(m1 - mn1);
            float sum0 = 0.f, sum1 = 0.f;
            for (int nt = 0; nt < ntmax; nt++) {
                int cc = nt * 8 + cq * 2;
                float p0 = expf(s[nt][0] - mn0);
                float p1 = expf(s[nt][1] - mn0);
                float p2 = expf(s[nt][2] - mn1);
                float p3 = expf(s[nt][3] - mn1);
                sum0 += p0 + p1;
                sum1 += p2 + p3;
                Ps[wm + r][cc] = p0;     Ps[wm + r][cc + 1] = p1;
                Ps[wm + r + 8][cc] = p2; Ps[wm + r + 8][cc + 1] = p3;
            }
            sum0 += __shfl_xor_sync(0xffffffffu, sum0, 1);
            sum0 += __shfl_xor_sync(0xffffffffu, sum0, 2);
            sum1 += __shfl_xor_sync(0xffffffffu, sum1, 1);
            sum1 += __shfl_xor_sync(0xffffffffu, sum1, 2);
            l0 = l0 * sc0 + sum0;
            l1 = l1 * sc1 + sum1;
            m0 = mn0; m1 = mn1;
#pragma unroll
            for (int nt = 0; nt < 8; nt++) {
                o[nt][0] *= sc0; o[nt][1] *= sc0;
                o[nt][2] *= sc1; o[nt][3] *= sc1;
            }
            __syncwarp();

            for (int k0 = 0; k0 < ntmax * 8; k0 += 8) {
                uint32_t ahi[4], alo[4];
                split_u(Ps[wm + r][k0 + cq],         ahi[0], alo[0]);
                split_u(Ps[wm + r + 8][k0 + cq],     ahi[1], alo[1]);
                split_u(Ps[wm + r][k0 + cq + 4],     ahi[2], alo[2]);
                split_u(Ps[wm + r + 8][k0 + cq + 4], ahi[3], alo[3]);
#pragma unroll
                for (int nt = 0; nt < 8; nt++) {
                    uint32_t bhi[2], blo[2];
                    split_u(Vt[nt * 8 + r][k0 + cq],     bhi[0], blo[0]);
                    split_u(Vt[nt * 8 + r][k0 + cq + 4], bhi[1], blo[1]);
                    MMA_TF32(o[nt], ahi, bhi);
                    MMA_TF32(o[nt], ahi, blo);
                    MMA_TF32(o[nt], alo, bhi);
                }
            }
        }
    }

    if (wactive) {
        const float inv0 = 1.0f / l0, inv1 = 1.0f / l1;
        const int row0 = i0 + wm + r, row1 = row0 + 8;
#pragma unroll
        for (int nt = 0; nt < 8; nt++) {
            const int col = h * HD + nt * 8 + cq * 2;
            if (row0 < SS) {
                float2 ov = make_float2(tf32r(o[nt][0] * inv0), tf32r(o[nt][1] * inv0));
                *(float2*)&ctx[((size_t)b * SS + row0) * DD + col] = ov;
            }
            if (row1 < SS) {
                float2 ov = make_float2(tf32r(o[nt][2] * inv1), tf32r(o[nt][3] * inv1));
                *(float2*)&ctx[((size_t)b * SS + row1) * DD + col] = ov;
            }
        }
    }
}

// ---------------- classifier head ----------------
__global__ void head_kernel(const float* __restrict__ cls, const float* __restrict__ hw,
                            float* __restrict__ out)
{
    __shared__ float s[DD];
    int b = blockIdx.x;
    for (int k = threadIdx.x; k < DD; k += blockDim.x) s[k] = cls[(size_t)b * DD + k];
    __syncthreads();
    int c = threadIdx.x;
    if (c < NCLS) {
        const float* w = hw + (size_t)c * DD;
        float acc = 0.f;
#pragma unroll 8
        for (int k = 0; k < DD; k++) acc += s[k] * w[k];
        out[(size_t)b * NCLS + c] = acc;
    }
}

// ---------------- launch ----------------
extern "C" void kernel_launch(void* const* d_in, const int* in_sizes, int n_in,
                              void* d_out, int out_size) {
    const float* x         = (const float*)d_in[0];
    const float* patch_w   = (const float*)d_in[1];
    const float* patch_b   = (const float*)d_in[2];
    const float* cls_token = (const float*)d_in[3];
    const float* pos_embed = (const float*)d_in[4];
    const float* ln1_g     = (const float*)d_in[5];
    const float* ln1_b     = (const float*)d_in[6];
    const float* qkv_w     = (const float*)d_in[7];
    const float* qkv_b     = (const float*)d_in[8];
    const float* out_w     = (const float*)d_in[9];
    const float* out_b     = (const float*)d_in[10];
    const float* ln2_g     = (const float*)d_in[11];
    const float* ln2_b     = (const float*)d_in[12];
    const float* fc1_w     = (const float*)d_in[13];
    const float* fc1_b     = (const float*)d_in[14];
    const float* fc2_w     = (const float*)d_in[15];
    const float* fc2_b     = (const float*)d_in[16];
    const float* lnf_g     = (const float*)d_in[17];
    const float* lnf_b     = (const float*)d_in[18];
    const float* head_w    = (const float*)d_in[19];
    float* out = (float*)d_out;

    float *patches, *tok, *h, *xn, *qkv, *ctx, *hid, *cls, *w;
    cudaGetSymbolAddress((void**)&patches, g_patches);
    cudaGetSymbolAddress((void**)&tok, g_tok);
    cudaGetSymbolAddress((void**)&h, g_h);
    cudaGetSymbolAddress((void**)&xn, g_xn);
    cudaGetSymbolAddress((void**)&qkv, g_qkv);
    cudaGetSymbolAddress((void**)&ctx, g_ctx);
    cudaGetSymbolAddress((void**)&hid, g_hid);
    cudaGetSymbolAddress((void**)&cls, g_cls);
    cudaGetSymbolAddress((void**)&w, g_w);

    cudaFuncSetAttribute(gemm_tf32<0>, cudaFuncAttributeMaxDynamicSharedMemorySize, GEMM_SMEM);
    cudaFuncSetAttribute(gemm_tf32<1>, cudaFuncAttributeMaxDynamicSharedMemorySize, GEMM_SMEM);
    cudaFuncSetAttribute(gemm_tf32<2>, cudaFuncAttributeMaxDynamicSharedMemorySize, GEMM_SMEM);
    cudaFuncSetAttribute(flash_attn, cudaFuncAttributeMaxDynamicSharedMemorySize, FA_SMEM);

    // 0,1: weight rounding; 2: patchify; 3: patch GEMM (profiled index)
    round_w_a<<<(W_FC1 / 4 + 255) / 256, 256>>>(patch_w, qkv_w, out_w, w);
    round_w_b<<<((W_TOTAL - W_FC1) / 4 + 255) / 256, 256>>>(fc1_w, fc2_w, w);
    patchify_kernel<<<(PTOK * PATCH_DIM + 255) / 256, 256>>>(x, patches);
    gemm_tf32<0><<<dim3(DD / 128, PTOK / 128), 256, GEMM_SMEM>>>(
        patches, w + W_PATCH, patch_b, nullptr, tok, PTOK, DD, PATCH_DIM);
    assemble_kernel<<<(TOK * DD + 255) / 256, 256>>>(tok, cls_token, pos_embed, h);

    for (int i = 0; i < DEPTH; i++) {
        ln_warp_kernel<<<(TOK + 7) / 8, 256>>>(h, ln1_g + i * DD, ln1_b + i * DD, xn, DD, TOK);
        gemm_tf32<0><<<dim3(3 * DD / 128, TOK / 128), 256, GEMM_SMEM>>>(
            xn, w + W_QKV + (size_t)i * 3 * DD * DD, qkv_b + (size_t)i * 3 * DD,
            nullptr, qkv, TOK, 3 * DD, DD);
        flash_attn<<<dim3(2, BH), 256, FA_SMEM>>>(qkv, ctx);
        gemm_tf32<2><<<dim3(DD / 128, TOK / 128), 256, GEMM_SMEM>>>(
            ctx, w + W_OUT + (size_t)i * DD * DD, out_b + (size_t)i * DD, h, h, TOK, DD, DD);
        ln_warp_kernel<<<(TOK + 7) / 8, 256>>>(h, ln2_g + i * DD, ln2_b + i * DD, xn, DD, TOK);
        gemm_tf32<1><<<dim3(HID / 128, TOK / 128), 256, GEMM_SMEM>>>(
            xn, w + W_FC1 + (size_t)i * HID * DD, fc1_b + (size_t)i * HID,
            nullptr, hid, TOK, HID, DD);
        gemm_tf32<2><<<dim3(DD / 128, TOK / 128), 256, GEMM_SMEM>>>(
            hid, w + W_FC2 + (size_t)i * DD * HID, fc2_b + (size_t)i * DD, h, h, TOK, DD, HID);
    }

    ln_warp_kernel<<<(BB + 7) / 8, 256>>>(h, lnf_g, lnf_b, cls, (long)SS * DD, BB);
    head_kernel<<<BB, 128>>>(cls, head_w, out);
}